// round 10
// baseline (speedup 1.0000x reference)
#include <cuda_runtime.h>
#include <cuda_bf16.h>
#include <cstdint>

// ---------------------------------------------------------------------------
// Scratch (device globals — no allocation allowed)
// ---------------------------------------------------------------------------
__device__ float g_h1[16*64*128*128];          // enc1 out / dec2 out (reused)
__device__ float g_h2[16*128*64*64];           // enc2 out / dec1 out (reused)
__device__ float g_h3[16*256*64*64];           // enc3 out
__device__ float g_z [16*256*64*64];           // enc4 out (z) / quantized NCHW (reused)
__device__ float g_resid[65536*256];
__device__ float g_qsum [65536*256];
__device__ double g_loss[4];
__device__ float g_cnorm[4*1024];
__device__ unsigned g_rowmin[65536];
__device__ float g_w4p[9*64*16];               // dec_w4 repacked [tau][ci][12 pad 16]
__device__ float g_wt[1310720];                // conv weights repacked [tap][ci][co]
__device__ float g_wtT[196608];                // convT weights [parity][tap][ci][co]
__device__ float g_d3[16*64*256*256];          // dec3 out; ALSO the 65536x1024 D (bf16)

// ---------------------------------------------------------------------------
// tf32 helpers
// ---------------------------------------------------------------------------
__device__ __forceinline__ uint32_t f2tf(float f) {
    uint32_t u;
    asm("cvt.rna.tf32.f32 %0, %1;" : "=r"(u) : "f"(f));
    return u;
}

__device__ __forceinline__ void split2(float x, uint32_t& h, uint32_t& l) {
    h = f2tf(x);
    l = f2tf(x - __uint_as_float(h));
}

__device__ __forceinline__ void mma_tf32(float* c, const uint32_t* a,
                                         uint32_t b0, uint32_t b1) {
    asm volatile(
        "mma.sync.aligned.m16n8k8.row.col.f32.tf32.tf32.f32 "
        "{%0,%1,%2,%3},{%4,%5,%6,%7},{%8,%9},{%0,%1,%2,%3};"
        : "+f"(c[0]), "+f"(c[1]), "+f"(c[2]), "+f"(c[3])
        : "r"(a[0]), "r"(a[1]), "r"(a[2]), "r"(a[3]), "r"(b0), "r"(b1));
}

// order-preserving float <-> uint32 (for atomicMin)
__device__ __forceinline__ unsigned fenc(float d) {
    unsigned u = __float_as_uint(d);
    return (u & 0x80000000u) ? ~u : (u | 0x80000000u);
}
__device__ __forceinline__ float fdec(unsigned e) {
    unsigned u = (e & 0x80000000u) ? (e & 0x7FFFFFFFu) : ~e;
    return __uint_as_float(u);
}

static const int PLW  = 128*33;   // A/D plane (words), stride 33: conflict-free
static const int BPLW = 64*33;    // B plane for N=64 tiles

// ---------------------------------------------------------------------------
// Phase A: approximate distance matrix, single tf32 MMA, D stored as bf16.
// D[m,n] = cn[n] - 2 * R[m,:].cb[n,:]; per-row min -> rowmin (atomicMin).
// ---------------------------------------------------------------------------
__global__ __launch_bounds__(256)
void vq_gemm_approx(const float* __restrict__ R, const float* __restrict__ cb,
                    const float* __restrict__ cn, __nv_bfloat16* __restrict__ D,
                    unsigned* __restrict__ rowmin)
{
    extern __shared__ uint32_t dyn[];
    uint32_t* sA = dyn;
    uint32_t* sB = dyn + PLW;
    unsigned* sMin = (unsigned*)(dyn + 2*PLW);

    const int tid  = threadIdx.x;
    const int lane = tid & 31;
    const int warp = tid >> 5;
    const int wm = warp & 1;
    const int wn = warp >> 1;
    const int m0 = blockIdx.x << 7;
    const int n0 = blockIdx.y << 7;

    float acc[4][4][4];
#pragma unroll
    for (int i = 0; i < 4; i++)
#pragma unroll
        for (int j = 0; j < 4; j++)
#pragma unroll
            for (int k = 0; k < 4; k++) acc[i][j][k] = 0.f;

    if (tid < 128) sMin[tid] = 0xFFFFFFFFu;

    for (int k0 = 0; k0 < 256; k0 += 32) {
#pragma unroll
        for (int i = 0; i < 4; i++) {
            int idx4 = tid + i*256;
            int m  = idx4 >> 3;
            int kq = idx4 & 7;
            int oa = m*33 + kq*4;
            float4 a = *(const float4*)(R  + (size_t)(m0 + m)*256 + k0 + kq*4);
            sA[oa+0] = f2tf(a.x); sA[oa+1] = f2tf(a.y);
            sA[oa+2] = f2tf(a.z); sA[oa+3] = f2tf(a.w);
            float4 b = *(const float4*)(cb + (size_t)(n0 + m)*256 + k0 + kq*4);
            sB[oa+0] = f2tf(b.x); sB[oa+1] = f2tf(b.y);
            sB[oa+2] = f2tf(b.z); sB[oa+3] = f2tf(b.w);
        }
        __syncthreads();

#pragma unroll
        for (int ks = 0; ks < 4; ks++) {
            const int kb = ks*8 + (lane & 3);
            uint32_t bf[4][2];
#pragma unroll
            for (int fn = 0; fn < 4; fn++) {
                int n = wn*32 + fn*8 + (lane >> 2);
                bf[fn][0] = sB[n*33 + kb];  bf[fn][1] = sB[n*33 + kb + 4];
            }
#pragma unroll
            for (int fm = 0; fm < 4; fm++) {
                int r = wm*64 + fm*16 + (lane >> 2);
                uint32_t af[4];
                af[0] = sA[r*33 + kb];     af[1] = sA[(r+8)*33 + kb];
                af[2] = sA[r*33 + kb+4];   af[3] = sA[(r+8)*33 + kb+4];
#pragma unroll
                for (int fn = 0; fn < 4; fn++)
                    mma_tf32(acc[fm][fn], af, bf[fn][0], bf[fn][1]);
            }
        }
        __syncthreads();
    }

    float cnv[4][2];
#pragma unroll
    for (int fn = 0; fn < 4; fn++) {
        int col = n0 + wn*32 + fn*8 + 2*(lane & 3);
        cnv[fn][0] = cn[col];
        cnv[fn][1] = cn[col + 1];
    }
#pragma unroll
    for (int fm = 0; fm < 4; fm++) {
#pragma unroll
        for (int h = 0; h < 2; h++) {
            int rl = wm*64 + fm*16 + (lane >> 2) + h*8;
            int rg = m0 + rl;
            float mn = 3.402823466e38f;
#pragma unroll
            for (int fn = 0; fn < 4; fn++) {
                int col = n0 + wn*32 + fn*8 + 2*(lane & 3);
                float vx = cnv[fn][0] - 2.f*acc[fm][fn][h*2 + 0];
                float vy = cnv[fn][1] - 2.f*acc[fm][fn][h*2 + 1];
                mn = fminf(mn, fminf(vx, vy));
                *(__nv_bfloat162*)(D + (size_t)rg*1024 + col) =
                    __floats2bfloat162_rn(vx, vy);
            }
            atomicMin(&sMin[rl], fenc(mn));
        }
    }
    __syncthreads();
    if (tid < 128) atomicMin(&rowmin[m0 + tid], sMin[tid]);
}

__global__ void init_rowmin(unsigned* rowmin) {
    rowmin[blockIdx.x*1024 + threadIdx.x] = 0xFFFFFFFFu;
}

// ---------------------------------------------------------------------------
// Phase B: one warp per token; exact-FFMA rescore of candidates within EPS of
// the approx row-min, lowest-index tie-break, fused vq_update.
// ---------------------------------------------------------------------------
__global__ __launch_bounds__(256)
void vq_select_update(const __nv_bfloat16* __restrict__ D, const float* __restrict__ cb,
                      const float* __restrict__ cn,
                      const unsigned* __restrict__ rowmin,
                      float* __restrict__ resid, float* __restrict__ qsum,
                      float* __restrict__ idx_out, int stage,
                      double* __restrict__ lossAcc)
{
    __shared__ double sLoss[8];
    const int warp = threadIdx.x >> 5;
    const int lane = threadIdx.x & 31;
    const int t = blockIdx.x*8 + warp;

    const __nv_bfloat16* drow = D + (size_t)t*1024;
    const float thr = fdec(rowmin[t]) + 0.03f;

    float4 r0 = *(const float4*)(resid + (size_t)t*256 + lane*8);
    float4 r1 = *(const float4*)(resid + (size_t)t*256 + lane*8 + 4);

    float bestd = 3.402823466e38f;
    int   bestn = 0;
    for (int j0 = 0; j0 < 1024; j0 += 32) {
        float dv = __bfloat162float(drow[j0 + lane]);
        unsigned m = __ballot_sync(0xffffffffu, dv <= thr);
        while (m) {
            int src = __ffs(m) - 1; m &= m - 1;
            int j = j0 + src;
            const float* c = cb + (size_t)j*256;
            float4 c0 = *(const float4*)(c + lane*8);
            float4 c1 = *(const float4*)(c + lane*8 + 4);
            float dot = r0.x*c0.x + r0.y*c0.y + r0.z*c0.z + r0.w*c0.w
                      + r1.x*c1.x + r1.y*c1.y + r1.z*c1.z + r1.w*c1.w;
#pragma unroll
            for (int o = 16; o; o >>= 1)
                dot += __shfl_xor_sync(0xffffffffu, dot, o);
            float de = cn[j] - 2.f*dot;
            if (de < bestd) { bestd = de; bestn = j; }
        }
    }

    const float* q = cb + (size_t)bestn*256;
    float4 q0 = *(const float4*)(q + lane*8);
    float4 q1 = *(const float4*)(q + lane*8 + 4);
    float4 s0 = *(float4*)(qsum + (size_t)t*256 + lane*8);
    float4 s1 = *(float4*)(qsum + (size_t)t*256 + lane*8 + 4);

    float ls = 0.f;
    {
        float d;
        d = q0.x-r0.x; ls += d*d;  d = q0.y-r0.y; ls += d*d;
        d = q0.z-r0.z; ls += d*d;  d = q0.w-r0.w; ls += d*d;
        d = q1.x-r1.x; ls += d*d;  d = q1.y-r1.y; ls += d*d;
        d = q1.z-r1.z; ls += d*d;  d = q1.w-r1.w; ls += d*d;
    }
    s0.x += q0.x; s0.y += q0.y; s0.z += q0.z; s0.w += q0.w;
    s1.x += q1.x; s1.y += q1.y; s1.z += q1.z; s1.w += q1.w;
    r0.x -= q0.x; r0.y -= q0.y; r0.z -= q0.z; r0.w -= q0.w;
    r1.x -= q1.x; r1.y -= q1.y; r1.z -= q1.z; r1.w -= q1.w;
    *(float4*)(qsum  + (size_t)t*256 + lane*8)     = s0;
    *(float4*)(qsum  + (size_t)t*256 + lane*8 + 4) = s1;
    *(float4*)(resid + (size_t)t*256 + lane*8)     = r0;
    *(float4*)(resid + (size_t)t*256 + lane*8 + 4) = r1;

#pragma unroll
    for (int o = 16; o; o >>= 1) ls += __shfl_down_sync(0xffffffffu, ls, o);
    if (lane == 0) {
        sLoss[warp] = (double)ls;
        idx_out[(t >> 12)*16384 + stage*4096 + (t & 4095)] = (float)bestn;
    }
    __syncthreads();
    if (threadIdx.x == 0) {
        double tot = 0.0;
#pragma unroll
        for (int w = 0; w < 8; w++) tot += sLoss[w];
        atomicAdd(lossAcc + stage, tot);
    }
}

// ---------------------------------------------------------------------------
// dec1 3x3 conv on tensor cores, split2 tf32 (3 MMA) — decoder-only accuracy.
// M=128 px x N=128 co, K=9*Cin. H=W=64. Dynamic smem: 4 planes = 67584 B.
// ---------------------------------------------------------------------------
__global__ __launch_bounds__(256)
void conv3x3_tc(const float* __restrict__ in, const float* __restrict__ wt,
                const float* __restrict__ bias, float* __restrict__ out,
                int Cin, int Cout, int relu)
{
    extern __shared__ uint32_t dyn[];
    uint32_t* sAh = dyn;
    uint32_t* sAl = dyn + PLW;
    uint32_t* sBh = dyn + 2*PLW;
    uint32_t* sBl = dyn + 3*PLW;

    const int tid  = threadIdx.x;
    const int lane = tid & 31;
    const int warp = tid >> 5;
    const int wm = warp & 1;
    const int wn = warp >> 1;
    const int m0  = blockIdx.x << 7;
    const int co0 = blockIdx.y << 7;
    const int b   = m0 >> 12;
    const int y0  = (m0 & 4095) >> 6;

    float acc[4][4][4];
#pragma unroll
    for (int i = 0; i < 4; i++)
#pragma unroll
        for (int j = 0; j < 4; j++)
#pragma unroll
            for (int k = 0; k < 4; k++) acc[i][j][k] = 0.f;

    for (int tap = 0; tap < 9; tap++) {
        const int dy = tap/3 - 1, dx = tap%3 - 1;
        for (int ci0 = 0; ci0 < Cin; ci0 += 32) {
#pragma unroll
            for (int v = 0; v < 16; v++) {
                int idx = tid + v*256;
                int ci = idx >> 7, pix = idx & 127;
                int iy = y0 + (pix >> 6) + dy;
                int ix = (pix & 63) + dx;
                float val = 0.f;
                if ((unsigned)iy < 64u && (unsigned)ix < 64u)
                    val = in[((size_t)(b*Cin + ci0 + ci)*64 + iy)*64 + ix];
                split2(val, sAh[pix*33 + ci], sAl[pix*33 + ci]);
            }
#pragma unroll
            for (int v = 0; v < 16; v++) {
                int idx = tid + v*256;
                int ci = idx >> 7, n = idx & 127;
                float val = wt[((size_t)tap*Cin + ci0 + ci)*Cout + co0 + n];
                split2(val, sBh[n*33 + ci], sBl[n*33 + ci]);
            }
            __syncthreads();

#pragma unroll
            for (int ks = 0; ks < 4; ks++) {
                const int kb = ks*8 + (lane & 3);
                uint32_t bh[4][2], bl[4][2];
#pragma unroll
                for (int fn = 0; fn < 4; fn++) {
                    int n = wn*32 + fn*8 + (lane >> 2);
                    bh[fn][0] = sBh[n*33 + kb];  bh[fn][1] = sBh[n*33 + kb + 4];
                    bl[fn][0] = sBl[n*33 + kb];  bl[fn][1] = sBl[n*33 + kb + 4];
                }
#pragma unroll
                for (int fm = 0; fm < 4; fm++) {
                    int r = wm*64 + fm*16 + (lane >> 2);
                    uint32_t ah[4], al[4];
                    ah[0] = sAh[r*33 + kb];     ah[1] = sAh[(r+8)*33 + kb];
                    ah[2] = sAh[r*33 + kb+4];   ah[3] = sAh[(r+8)*33 + kb+4];
                    al[0] = sAl[r*33 + kb];     al[1] = sAl[(r+8)*33 + kb];
                    al[2] = sAl[r*33 + kb+4];   al[3] = sAl[(r+8)*33 + kb+4];
#pragma unroll
                    for (int fn = 0; fn < 4; fn++) {
                        mma_tf32(acc[fm][fn], al, bh[fn][0], bh[fn][1]);
                        mma_tf32(acc[fm][fn], ah, bl[fn][0], bl[fn][1]);
                        mma_tf32(acc[fm][fn], ah, bh[fn][0], bh[fn][1]);
                    }
                }
            }
            __syncthreads();
        }
    }

    // epilogue: bias (+relu), NCHW scatter stores
#pragma unroll
    for (int fn = 0; fn < 4; fn++) {
        int col = co0 + wn*32 + fn*8 + 2*(lane & 3);
        float bv0 = bias[col], bv1 = bias[col + 1];
#pragma unroll
        for (int fm = 0; fm < 4; fm++) {
#pragma unroll
            for (int h = 0; h < 2; h++) {
                int r = wm*64 + fm*16 + (lane >> 2) + h*8;
                int y = y0 + (r >> 6);
                int x = r & 63;
                float v0 = acc[fm][fn][h*2 + 0] + bv0;
                float v1 = acc[fm][fn][h*2 + 1] + bv1;
                if (relu) { v0 = fmaxf(v0, 0.f); v1 = fmaxf(v1, 0.f); }
                out[(((size_t)b*Cout + col    )*64 + y)*64 + x] = v0;
                out[(((size_t)b*Cout + col + 1)*64 + y)*64 + x] = v1;
            }
        }
    }
}

// ---------------------------------------------------------------------------
// convT (k4 s2 p1) on tensor cores, split2 tf32, parity-decomposed, Cout=64.
// M=128 input px x N=64 co, K=4*Cin per parity. relu.
// Dynamic smem: 2 A planes + 2 B planes = 50688 B.
// ---------------------------------------------------------------------------
__global__ __launch_bounds__(256)
void convT_tc(const float* __restrict__ in, const float* __restrict__ wtT,
              const float* __restrict__ bias, float* __restrict__ out,
              int Cin, int Hin, int Win, int wsh, int hwsh)
{
    extern __shared__ uint32_t dyn[];
    uint32_t* sAh = dyn;
    uint32_t* sAl = dyn + PLW;
    uint32_t* sBh = dyn + 2*PLW;
    uint32_t* sBl = dyn + 2*PLW + BPLW;

    const int tid  = threadIdx.x;
    const int lane = tid & 31;
    const int warp = tid >> 5;
    const int wm = warp & 1;        // 2 groups of 64 rows
    const int wn = warp >> 1;       // 4 groups of 16 cols
    const int P0 = blockIdx.x << 7;
    const int b  = P0 >> hwsh;
    const int lp = P0 & ((1 << hwsh) - 1);
    const int p  = blockIdx.z;
    const int ey = p >> 1, ex = p & 1;
    const float* wtp = wtT + (size_t)p*4*Cin*64;
    const int Wo  = Win*2;
    const int HWo = (Hin*Win)*4;

    float acc[4][2][4];
#pragma unroll
    for (int i = 0; i < 4; i++)
#pragma unroll
        for (int j = 0; j < 2; j++)
#pragma unroll
            for (int k = 0; k < 4; k++) acc[i][j][k] = 0.f;

    for (int t = 0; t < 4; t++) {
        const int jy = t >> 1, jx = t & 1;
        const int ry = (ey == 0) ? (jy == 0 ? 0 : -1) : (jy == 0 ? 1 : 0);
        const int rx = (ex == 0) ? (jx == 0 ? 0 : -1) : (jx == 0 ? 1 : 0);
        for (int ci0 = 0; ci0 < Cin; ci0 += 32) {
#pragma unroll
            for (int v = 0; v < 16; v++) {
                int idx = tid + v*256;
                int ci = idx >> 7, pix = idx & 127;
                int gp = lp + pix;
                int iy = (gp >> wsh) + ry;
                int ix = (gp & (Win-1)) + rx;
                float val = 0.f;
                if ((unsigned)iy < (unsigned)Hin && (unsigned)ix < (unsigned)Win)
                    val = in[((size_t)(b*Cin + ci0 + ci)*Hin + iy)*Win + ix];
                split2(val, sAh[pix*33 + ci], sAl[pix*33 + ci]);
            }
#pragma unroll
            for (int v = 0; v < 8; v++) {
                int idx = tid + v*256;
                int ci = idx >> 6, n = idx & 63;
                float val = wtp[((size_t)t*Cin + ci0 + ci)*64 + n];
                split2(val, sBh[n*33 + ci], sBl[n*33 + ci]);
            }
            __syncthreads();

#pragma unroll
            for (int ks = 0; ks < 4; ks++) {
                const int kb = ks*8 + (lane & 3);
                uint32_t bh[2][2], bl[2][2];
#pragma unroll
                for (int fn = 0; fn < 2; fn++) {
                    int n = wn*16 + fn*8 + (lane >> 2);
                    bh[fn][0] = sBh[n*33 + kb];  bh[fn][1] = sBh[n*33 + kb + 4];
                    bl[fn][0] = sBl[n*33 + kb];  bl[fn][1] = sBl[n*33 + kb + 4];
                }
#pragma unroll
                for (int fm = 0; fm < 4; fm++) {
                    int r = wm*64 + fm*16 + (lane >> 2);
                    uint32_t ah[4], al[4];
                    ah[0] = sAh[r*33 + kb];     ah[1] = sAh[(r+8)*33 + kb];
                    ah[2] = sAh[r*33 + kb+4];   ah[3] = sAh[(r+8)*33 + kb+4];
                    al[0] = sAl[r*33 + kb];     al[1] = sAl[(r+8)*33 + kb];
                    al[2] = sAl[r*33 + kb+4];   al[3] = sAl[(r+8)*33 + kb+4];
#pragma unroll
                    for (int fn = 0; fn < 2; fn++) {
                        mma_tf32(acc[fm][fn], al, bh[fn][0], bh[fn][1]);
                        mma_tf32(acc[fm][fn], ah, bl[fn][0], bl[fn][1]);
                        mma_tf32(acc[fm][fn], ah, bh[fn][0], bh[fn][1]);
                    }
                }
            }
            __syncthreads();
        }
    }

    // epilogue: bias + relu, strided parity stores
#pragma unroll
    for (int fn = 0; fn < 2; fn++) {
        int col = wn*16 + fn*8 + 2*(lane & 3);
        float bv0 = bias[col], bv1 = bias[col + 1];
#pragma unroll
        for (int fm = 0; fm < 4; fm++) {
#pragma unroll
            for (int h = 0; h < 2; h++) {
                int r  = wm*64 + fm*16 + (lane >> 2) + h*8;
                int gp = lp + r;
                int my = gp >> wsh, mx = gp & (Win-1);
                int oy = 2*my + ey;
                float v0 = fmaxf(acc[fm][fn][h*2 + 0] + bv0, 0.f);
                float v1 = fmaxf(acc[fm][fn][h*2 + 1] + bv1, 0.f);
                out[((size_t)(b*64 + col    ))*HWo + oy*Wo + 2*mx + ex] = v0;
                out[((size_t)(b*64 + col + 1))*HWo + oy*Wo + 2*mx + ex] = v1;
            }
        }
    }
}

// ---------------------------------------------------------------------------
// Implicit-GEMM FFMA conv (3x3 s1 or 4x4 s2, pad 1) — encoder (exact fp32).
// Double-buffered smem, register-staged prefetch.
// ---------------------------------------------------------------------------
template<int KSZ, int S>
__global__ __launch_bounds__(256, 2)
void conv_ffma(const float* __restrict__ in, const float* __restrict__ wt,
               const float* __restrict__ bias, float* __restrict__ out,
               int Cin, int Hin, int Win, int Cout, int relu)
{
    __shared__ float sA[2][16*128];
    __shared__ float sB[2][16*128];
    const int tid = threadIdx.x;
    const int tx = tid & 15;
    const int ty = tid >> 4;
    const int m0  = blockIdx.x << 7;
    const int co0 = blockIdx.y << 7;
    const int b   = m0 >> 12;
    const int y0  = (m0 & 4095) >> 6;
    const int cpt = Cin >> 4;
    const int NCH = KSZ*KSZ*cpt;

    float acc[8][8];
#pragma unroll
    for (int i = 0; i < 8; i++)
#pragma unroll
        for (int j = 0; j < 8; j++) acc[i][j] = 0.f;

    float ra[8], rb[8];

    auto loadc = [&](int q) {
        int tap = q / cpt;
        int ci0 = (q - tap*cpt) << 4;
        int dy = tap/KSZ - 1, dx = tap%KSZ - 1;
#pragma unroll
        for (int v = 0; v < 8; v++) {
            int idx = tid + v*256;
            int ci = idx >> 7, pix = idx & 127;
            int iy = (y0 + (pix >> 6))*S + dy;
            int ix = (pix & 63)*S + dx;
            float val = 0.f;
            if ((unsigned)iy < (unsigned)Hin && (unsigned)ix < (unsigned)Win)
                val = in[((size_t)(b*Cin + ci0 + ci)*Hin + iy)*Win + ix];
            ra[v] = val;
            rb[v] = wt[((size_t)tap*Cin + ci0 + ci)*Cout + co0 + pix];
        }
    };
    auto storec = [&](int buf) {
#pragma unroll
        for (int v = 0; v < 8; v++) {
            int idx = tid + v*256;
            int ci = idx >> 7, pix = idx & 127;
            sA[buf][ci*128 + pix] = ra[v];
            sB[buf][ci*128 + pix] = rb[v];
        }
    };

    loadc(0); storec(0); __syncthreads();
    for (int q = 0; q < NCH; q++) {
        if (q + 1 < NCH) loadc(q + 1);
        const float* pA = sA[q & 1];
        const float* pB = sB[q & 1];
#pragma unroll
        for (int kk = 0; kk < 16; kk++) {
            float4 a0 = *(const float4*)&pA[kk*128 + tx*8];
            float4 a1 = *(const float4*)&pA[kk*128 + tx*8 + 4];
            float4 b0 = *(const float4*)&pB[kk*128 + ty*8];
            float4 b1 = *(const float4*)&pB[kk*128 + ty*8 + 4];
            float av[8] = {a0.x,a0.y,a0.z,a0.w,a1.x,a1.y,a1.z,a1.w};
            float bv[8] = {b0.x,b0.y,b0.z,b0.w,b1.x,b1.y,b1.z,b1.w};
#pragma unroll
            for (int i = 0; i < 8; i++)
#pragma unroll
                for (int j = 0; j < 8; j++) acc[i][j] += av[i]*bv[j];
        }
        __syncthreads();
        if (q + 1 < NCH) storec((q + 1) & 1);
        __syncthreads();
    }

    const int yr = y0 + (tx >> 3);
    const int xc = (tx*8) & 63;
#pragma unroll
    for (int j = 0; j < 8; j++) {
        int co = co0 + ty*8 + j;
        float bv = bias[co];
        float4 v0, v1;
        v0.x = acc[0][j]+bv; v0.y = acc[1][j]+bv; v0.z = acc[2][j]+bv; v0.w = acc[3][j]+bv;
        v1.x = acc[4][j]+bv; v1.y = acc[5][j]+bv; v1.z = acc[6][j]+bv; v1.w = acc[7][j]+bv;
        if (relu) {
            v0.x = fmaxf(v0.x,0.f); v0.y = fmaxf(v0.y,0.f); v0.z = fmaxf(v0.z,0.f); v0.w = fmaxf(v0.w,0.f);
            v1.x = fmaxf(v1.x,0.f); v1.y = fmaxf(v1.y,0.f); v1.z = fmaxf(v1.z,0.f); v1.w = fmaxf(v1.w,0.f);
        }
        float* p = out + ((size_t)(b*Cout + co)*4096 + yr*64 + xc);
        *(float4*)p = v0;
        *(float4*)(p + 4) = v1;
    }
}

// ---------------------------------------------------------------------------
// convT4 (k4 s2 p1, Cin=64 -> Cout=3, tanh): N=12 GEMM over shared A rows.
// Weights wp[tau(9)][ci(64)][12 pad 16]. Dynamic smem 59904 B.
// ---------------------------------------------------------------------------
__global__ __launch_bounds__(256)
void convT4_ffma(const float* __restrict__ in, const float* __restrict__ wp,
                 const float* __restrict__ bias, float* __restrict__ out)
{
    extern __shared__ float dynf[];
    float* sA = dynf;              // [16 ci][3 rows][264]
    float* sB = dynf + 16*792;     // [9 tau][16 ci][16]

    const int tid = threadIdx.x;
    const int b  = blockIdx.x >> 8;
    const int my = blockIdx.x & 255;
    const float* inb = in + (size_t)b*64*65536;

    float acc[12];
#pragma unroll
    for (int i = 0; i < 12; i++) acc[i] = 0.f;

    for (int ci0 = 0; ci0 < 64; ci0 += 16) {
        for (int idx = tid; idx < 16*3*258; idx += 256) {
            int ci = idx / 774;
            int rem = idx - ci*774;
            int r = rem / 258, c = rem - r*258;
            int iy = my - 1 + r, ix = c - 1;
            float v = 0.f;
            if ((unsigned)iy < 256u && (unsigned)ix < 256u)
                v = inb[((size_t)(ci0 + ci)*256 + iy)*256 + ix];
            sA[ci*792 + r*264 + c] = v;
        }
        for (int idx = tid; idx < 9*16*16; idx += 256) {
            int tau = idx >> 8;
            int rem = idx & 255;
            int ci = rem >> 4, s = rem & 15;
            sB[(tau*16 + ci)*16 + s] = wp[((size_t)tau*64 + ci0 + ci)*16 + s];
        }
        __syncthreads();

        for (int ci = 0; ci < 16; ci++) {
#pragma unroll
            for (int tau = 0; tau < 9; tau++) {
                float a = sA[ci*792 + (tau/3)*264 + (tau%3) + tid];
                const float4* bp = (const float4*)&sB[(tau*16 + ci)*16];
                float4 b0 = bp[0], b1 = bp[1], b2 = bp[2];
                acc[0] += a*b0.x; acc[1]  += a*b0.y; acc[2]  += a*b0.z;
                acc[3] += a*b0.w; acc[4]  += a*b1.x; acc[5]  += a*b1.y;
                acc[6] += a*b1.z; acc[7]  += a*b1.w; acc[8]  += a*b2.x;
                acc[9] += a*b2.y; acc[10] += a*b2.z; acc[11] += a*b2.w;
            }
        }
        __syncthreads();
    }

    const int mx = tid;
#pragma unroll
    for (int p = 0; p < 4; p++) {
        int ey = p >> 1, ex = p & 1;
        int oy = 2*my + ey;
#pragma unroll
        for (int co = 0; co < 3; co++) {
            float v = tanhf(acc[p*3 + co] + bias[co]);
            out[(((size_t)b*3 + co)*512 + oy)*512 + 2*mx + ex] = v;
        }
    }
}

// ---------------------------------------------------------------------------
// Fused weight repack (single launch)
// ---------------------------------------------------------------------------
__device__ __forceinline__ void rp_conv(const float* w, float* wt,
                                        int Cin, int Cout, int KK, int idx)
{
    int co = idx % Cout; int r = idx / Cout;
    int ci = r % Cin;    int tap = r / Cin;
    wt[idx] = w[(co*Cin + ci)*KK + tap];
}

__device__ __forceinline__ void rp_convT(const float* w, float* wtT,
                                         int Cin, int Cout, int idx)
{
    int co = idx % Cout; int r = idx / Cout;
    int ci = r % Cin;    int pt = r / Cin;
    int p = pt >> 2, t = pt & 3;
    int ey = p >> 1, ex = p & 1;
    int jy = t >> 1, jx = t & 1;
    int ky = (ey == 0) ? (jy == 0 ? 1 : 3) : (jy == 0 ? 0 : 2);
    int kx = (ex == 0) ? (jx == 0 ? 1 : 3) : (jx == 0 ? 0 : 2);
    wtT[idx] = w[((ci*Cout + co)*4 + ky)*4 + kx];
}

__device__ __forceinline__ void rp_w4(const float* w, float* wp, int idx)
{
    int tau = idx >> 10;
    int rem = idx & 1023;
    int ci = rem >> 4, s = rem & 15;
    float v = 0.f;
    if (s < 12) {
        int p = s / 3, co = s - p*3;
        int ey = p >> 1, ex = p & 1;
        int dy = tau/3 - 1, dx = tau%3 - 1;
        int ky = -1, kx = -1;
        if (ey == 0) { if (dy == 0) ky = 1; else if (dy == -1) ky = 3; }
        else         { if (dy == 1) ky = 0; else if (dy ==  0) ky = 2; }
        if (ex == 0) { if (dx == 0) kx = 1; else if (dx == -1) kx = 3; }
        else         { if (dx == 1) kx = 0; else if (dx ==  0) kx = 2; }
        if (ky >= 0 && kx >= 0)
            v = w[((ci*3 + co)*4 + ky)*4 + kx];
    }
    wp[idx] = v;
}

__global__ void repack_all(const float* ew2, const float* ew3, const float* ew4,
                           const float* dw1, const float* dw2, const float* dw3,
                           const float* dw4,
                           float* wt_e2, float* wt_e3, float* wt_e4, float* wt_d1,
                           float* wtT_d2, float* wtT_d3, float* w4p)
{
    int idx = blockIdx.x*256 + threadIdx.x;
    if (idx < 131072) { rp_conv(ew2, wt_e2, 64, 128, 16, idx); return; }
    idx -= 131072;
    if (idx < 294912) { rp_conv(ew3, wt_e3, 128, 256, 9, idx); return; }
    idx -= 294912;
    if (idx < 589824) { rp_conv(ew4, wt_e4, 256, 256, 9, idx); return; }
    idx -= 589824;
    if (idx < 294912) { rp_conv(dw1, wt_d1, 256, 128, 9, idx); return; }
    idx -= 294912;
    if (idx < 131072) { rp_convT(dw2, wtT_d2, 128, 64, idx); return; }
    idx -= 131072;
    if (idx < 65536)  { rp_convT(dw3, wtT_d3, 64, 64, idx); return; }
    idx -= 65536;
    if (idx < 9216)   { rp_w4(dw4, w4p, idx); }
}

// ---------------------------------------------------------------------------
// Direct conv (FFMA) — enc1 only (Cin=3).
// ---------------------------------------------------------------------------
template<int K, int S, int CIN_T>
__global__ __launch_bounds__(128)
void conv2d_tiled(const float* __restrict__ in, const float* __restrict__ w,
                  const float* __restrict__ bias, float* __restrict__ out,
                  int Cin, int H, int W, int Cout, int Ho, int Wo,
                  int pad, int relu)
{
    constexpr int IH = 3*S + K;
    constexpr int IW = 15*S + K;
    constexpr int KK = K*K;
    __shared__ __align__(16) float s_in[CIN_T*IH*IW];
    __shared__ __align__(16) float s_w [CIN_T*KK*64];

    const int tid = threadIdx.x;
    const int px  = tid & 15;
    const int cg  = tid >> 4;
    const int hb  = Ho >> 2;
    const int b   = blockIdx.y / hb;
    const int oy0 = (blockIdx.y % hb) * 4;
    const int ox0 = blockIdx.x * 16;
    const int co0 = blockIdx.z * 64;
    const int iy0 = oy0*S - pad;
    const int ix0 = ox0*S - pad;

    float acc[4][8];
#pragma unroll
    for (int p = 0; p < 4; p++)
#pragma unroll
        for (int c = 0; c < 8; c++) acc[p][c] = 0.f;

    for (int ci0 = 0; ci0 < Cin; ci0 += CIN_T) {
        for (int idx = tid; idx < CIN_T*IH*IW; idx += 128) {
            int ci  = idx / (IH*IW);
            int rem = idx % (IH*IW);
            int r   = rem / IW, c = rem % IW;
            int iy  = iy0 + r, ix = ix0 + c;
            float v = 0.f;
            if ((unsigned)iy < (unsigned)H && (unsigned)ix < (unsigned)W &&
                (ci0 + ci) < Cin)
                v = in[((b*Cin + ci0 + ci)*H + iy)*W + ix];
            s_in[idx] = v;
        }
        for (int idx = tid; idx < CIN_T*KK*64; idx += 128) {
            int co  = idx & 63;
            int rem = idx >> 6;
            int kk  = rem % KK;
            int ci  = rem / KK;
            float v = 0.f;
            if ((ci0 + ci) < Cin)
                v = w[((co0 + co)*Cin + ci0 + ci)*KK + kk];
            s_w[idx] = v;
        }
        __syncthreads();

        for (int ci = 0; ci < CIN_T; ci++) {
#pragma unroll
            for (int kh = 0; kh < K; kh++) {
#pragma unroll
                for (int kw = 0; kw < K; kw++) {
                    const float4* wp =
                        (const float4*)(s_w + ((ci*KK + kh*K + kw) << 6) + (cg << 3));
                    float4 w0 = wp[0], w1 = wp[1];
#pragma unroll
                    for (int p = 0; p < 4; p++) {
                        float iv = s_in[(ci*IH + p*S + kh)*IW + px*S + kw];
                        acc[p][0] += iv*w0.x; acc[p][1] += iv*w0.y;
                        acc[p][2] += iv*w0.z; acc[p][3] += iv*w0.w;
                        acc[p][4] += iv*w1.x; acc[p][5] += iv*w1.y;
                        acc[p][6] += iv*w1.z; acc[p][7] += iv*w1.w;
                    }
                }
            }
        }
        __syncthreads();
    }

#pragma unroll
    for (int c = 0; c < 8; c++) {
        int co = co0 + (cg << 3) + c;
        float bv = bias[co];
#pragma unroll
        for (int p = 0; p < 4; p++) {
            float v = acc[p][c] + bv;
            if (relu) v = fmaxf(v, 0.f);
            out[((b*Cout + co)*Ho + oy0 + p)*Wo + ox0 + px] = v;
        }
    }
}

// ---------------------------------------------------------------------------
// Helpers
// ---------------------------------------------------------------------------
__global__ void cnorm_kernel(const float* __restrict__ cb, float* __restrict__ cn) {
    int row  = (blockIdx.x*blockDim.x + threadIdx.x) >> 5;
    int lane = threadIdx.x & 31;
    if (row >= 4096) return;
    const float* p = cb + (size_t)row*256;
    float s = 0.f;
    for (int c = lane; c < 256; c += 32) { float v = p[c]; s += v*v; }
#pragma unroll
    for (int o = 16; o; o >>= 1) s += __shfl_down_sync(0xffffffffu, s, o);
    if (!lane) cn[row] = s;
}

__global__ void zero_loss(double* l) { if (threadIdx.x < 4) l[threadIdx.x] = 0.0; }

__global__ void write_loss(const double* __restrict__ l, float* __restrict__ o) {
    if (threadIdx.x < 4)
        o[threadIdx.x] = (float)(l[threadIdx.x] * (1.0/(65536.0*256.0)));
}

__global__ void z_to_tokens(const float* __restrict__ z,
                            float* __restrict__ resid, float* __restrict__ qsum)
{
    __shared__ float t[32][33];
    int b  = blockIdx.z;
    int s0 = blockIdx.x*32;
    int c0 = blockIdx.y*32;
    int x  = threadIdx.x;
    for (int y = threadIdx.y; y < 32; y += 8)
        t[y][x] = z[((size_t)b*256 + c0 + y)*4096 + s0 + x];
    __syncthreads();
    for (int y = threadIdx.y; y < 32; y += 8) {
        size_t o = ((size_t)b*4096 + s0 + y)*256 + c0 + x;
        resid[o] = t[x][y];
        qsum[o]  = 0.f;
    }
}

__global__ void tokens_to_z(const float* __restrict__ qsum,
                            float* __restrict__ z1, float* __restrict__ z2)
{
    __shared__ float t[32][33];
    int b  = blockIdx.z;
    int c0 = blockIdx.x*32;
    int s0 = blockIdx.y*32;
    int x  = threadIdx.x;
    for (int y = threadIdx.y; y < 32; y += 8)
        t[y][x] = qsum[((size_t)b*4096 + s0 + y)*256 + c0 + x];
    __syncthreads();
    for (int y = threadIdx.y; y < 32; y += 8) {
        float v = t[x][y];
        size_t o = ((size_t)b*256 + c0 + y)*4096 + s0 + x;
        z1[o] = v; z2[o] = v;
    }
}

// ---------------------------------------------------------------------------
// Launch
// ---------------------------------------------------------------------------
extern "C" void kernel_launch(void* const* d_in, const int* in_sizes, int n_in,
                              void* d_out, int out_size)
{
    const float* x   = (const float*)d_in[0];
    const float* ew1 = (const float*)d_in[1];  const float* eb1 = (const float*)d_in[2];
    const float* ew2 = (const float*)d_in[3];  const float* eb2 = (const float*)d_in[4];
    const float* ew3 = (const float*)d_in[5];  const float* eb3 = (const float*)d_in[6];
    const float* ew4 = (const float*)d_in[7];  const float* eb4 = (const float*)d_in[8];
    const float* cbs = (const float*)d_in[9];
    const float* dw1 = (const float*)d_in[10]; const float* db1 = (const float*)d_in[11];
    const float* dw2 = (const float*)d_in[12]; const float* db2 = (const float*)d_in[13];
    const float* dw3 = (const float*)d_in[14]; const float* db3 = (const float*)d_in[15];
    const float* dw4 = (const float*)d_in[16]; const float* db4 = (const float*)d_in[17];
    float* out = (float*)d_out;

    float *h1, *h2, *h3, *z, *resid, *qsum, *cnorm, *w4p, *wt, *wtT, *d3;
    double* loss; unsigned* rowmin;
    cudaGetSymbolAddress((void**)&h1,    g_h1);
    cudaGetSymbolAddress((void**)&h2,    g_h2);
    cudaGetSymbolAddress((void**)&h3,    g_h3);
    cudaGetSymbolAddress((void**)&z,     g_z);
    cudaGetSymbolAddress((void**)&resid, g_resid);
    cudaGetSymbolAddress((void**)&qsum,  g_qsum);
    cudaGetSymbolAddress((void**)&loss,  g_loss);
    cudaGetSymbolAddress((void**)&cnorm, g_cnorm);
    cudaGetSymbolAddress((void**)&rowmin,g_rowmin);
    cudaGetSymbolAddress((void**)&w4p,   g_w4p);
    cudaGetSymbolAddress((void**)&wt,    g_wt);
    cudaGetSymbolAddress((void**)&wtT,   g_wtT);
    cudaGetSymbolAddress((void**)&d3,    g_d3);

    float* wt_e2  = wt;                               // 16*64*128  = 131072
    float* wt_e3  = wt + 131072;                      // 9*128*256  = 294912
    float* wt_e4  = wt + 131072 + 294912;             // 9*256*256  = 589824
    float* wt_d1  = wt + 131072 + 294912 + 589824;    // 9*256*128  = 294912
    float* wtT_d2 = wtT;                              // 16*128*64  = 131072
    float* wtT_d3 = wtT + 131072;                     // 16*64*64   = 65536

    // output layout: recon | indices | commit_loss | quantized
    float* recO   = out;
    float* idxO   = out + 12582912;
    float* lossO  = idxO + 262144;
    float* quantO = lossO + 4;

    const int PA_SMEM  = 2*PLW*4 + 512;               // 34304
    const int C3_SMEM  = 4*PLW*4;                     // 67584
    const int CT_SMEM  = (2*PLW + 2*BPLW)*4;          // 50688
    const int CT4_SMEM = (16*792 + 9*16*16)*4;        // 59904
    cudaFuncSetAttribute(vq_gemm_approx, cudaFuncAttributeMaxDynamicSharedMemorySize, PA_SMEM);
    cudaFuncSetAttribute(conv3x3_tc,     cudaFuncAttributeMaxDynamicSharedMemorySize, C3_SMEM);
    cudaFuncSetAttribute(convT_tc,       cudaFuncAttributeMaxDynamicSharedMemorySize, CT_SMEM);
    cudaFuncSetAttribute(convT4_ffma,    cudaFuncAttributeMaxDynamicSharedMemorySize, CT4_SMEM);

    // prep (single fused repack => ncu -s 5 lands on enc3 conv_ffma)
    repack_all  <<<5924, 256>>>(ew2, ew3, ew4, dw1, dw2, dw3, dw4,
                                wt_e2, wt_e3, wt_e4, wt_d1, wtT_d2, wtT_d3, w4p);
    cnorm_kernel<<<512, 256>>>(cbs, cnorm);
    zero_loss   <<<1, 32>>>(loss);

    // ---- encoder (exact fp32) ----
    conv2d_tiled<4,2,4><<<dim3(8, 32*16, 1), 128>>>(x, ew1, eb1, h1, 3, 256, 256, 64, 128, 128, 1, 1);
    conv_ffma<4,2><<<dim3(512, 1), 256>>>(h1, wt_e2, eb2, h2,  64, 128, 128, 128, 1);
    conv_ffma<3,1><<<dim3(512, 2), 256>>>(h2, wt_e3, eb3, h3, 128,  64,  64, 256, 1);
    conv_ffma<3,1><<<dim3(512, 2), 256>>>(h3, wt_e4, eb4, z,  256,  64,  64, 256, 0);

    // ---- residual VQ: single-MMA tf32 approx distances (bf16 D) + exact rescore ----
    z_to_tokens<<<dim3(128, 8, 16), dim3(32, 8)>>>(z, resid, qsum);
    __nv_bfloat16* Dh = (__nv_bfloat16*)d3;
    for (int s = 0; s < 4; s++) {
        init_rowmin     <<<64, 1024>>>(rowmin);
        vq_gemm_approx  <<<dim3(512, 8), 256, PA_SMEM>>>(resid, cbs + (size_t)s*1024*256,
                                                         cnorm + s*1024, Dh, rowmin);
        vq_select_update<<<8192, 256>>>(Dh, cbs + (size_t)s*1024*256, cnorm + s*1024,
                                        rowmin, resid, qsum, idxO, s, loss);
    }
    write_loss <<<1, 32>>>(loss, lossO);
    tokens_to_z<<<dim3(8, 128, 16), dim3(32, 8)>>>(qsum, z, quantO);

    // ---- decoder (split2 tf32 tensor cores; recon-only accuracy budget) ----
    conv3x3_tc<<<dim3(512, 1), 256, C3_SMEM>>>(z, wt_d1, db1, h2, 256, 128, 1);
    convT_tc<<<dim3( 512, 1, 4), 256, CT_SMEM>>>(h2, wtT_d2, db2, h1, 128,  64,  64, 6, 12);
    convT_tc<<<dim3(2048, 1, 4), 256, CT_SMEM>>>(h1, wtT_d3, db3, d3,  64, 128, 128, 7, 14);
    convT4_ffma<<<4096, 256, CT4_SMEM>>>(d3, w4p, db4, recO);
}

// round 11
// speedup vs baseline: 1.1298x; 1.1298x over previous
#include <cuda_runtime.h>
#include <cuda_bf16.h>
#include <cstdint>

// ---------------------------------------------------------------------------
// Scratch (device globals — no allocation allowed)
// ---------------------------------------------------------------------------
__device__ float g_h1[16*64*128*128];          // enc1 out / dec2 out (reused)
__device__ float g_h2[16*128*64*64];           // enc2 out / dec1 out (reused)
__device__ float g_h3[16*256*64*64];           // enc3 out
__device__ float g_z [16*256*64*64];           // enc4 out (z) / quantized NCHW (reused)
__device__ float g_resid[65536*256];
__device__ float g_qsum [65536*256];
__device__ double g_loss[4];
__device__ float g_cnorm[4*1024];
__device__ unsigned g_rowmin[4*65536];
__device__ float g_w4p[9*64*16];               // dec_w4 repacked [tau][ci][12 pad 16]
__device__ float g_wt[1310720];                // conv weights repacked [tap][ci][co]
__device__ float g_wtT[196608];                // convT weights [parity][tap][ci][co]
__device__ float g_d3[16*64*256*256];          // dec3 out; ALSO the 65536x1024 D (bf16)

// ---------------------------------------------------------------------------
// tf32 helpers (approximate Phase-A path only; correctness never depends on it)
// ---------------------------------------------------------------------------
__device__ __forceinline__ uint32_t f2tf(float f) {
    uint32_t u;
    asm("cvt.rna.tf32.f32 %0, %1;" : "=r"(u) : "f"(f));
    return u;
}

__device__ __forceinline__ void mma_tf32(float* c, const uint32_t* a,
                                         uint32_t b0, uint32_t b1) {
    asm volatile(
        "mma.sync.aligned.m16n8k8.row.col.f32.tf32.tf32.f32 "
        "{%0,%1,%2,%3},{%4,%5,%6,%7},{%8,%9},{%0,%1,%2,%3};"
        : "+f"(c[0]), "+f"(c[1]), "+f"(c[2]), "+f"(c[3])
        : "r"(a[0]), "r"(a[1]), "r"(a[2]), "r"(a[3]), "r"(b0), "r"(b1));
}

// order-preserving float <-> uint32 (for atomicMin)
__device__ __forceinline__ unsigned fenc(float d) {
    unsigned u = __float_as_uint(d);
    return (u & 0x80000000u) ? ~u : (u | 0x80000000u);
}
__device__ __forceinline__ float fdec(unsigned e) {
    unsigned u = (e & 0x80000000u) ? (e & 0x7FFFFFFFu) : ~e;
    return __uint_as_float(u);
}

static const int PLW = 128*33;   // one smem plane in words (stride 33: conflict-free)

// ---------------------------------------------------------------------------
// Phase A: approximate distance matrix, single tf32 MMA, D stored as bf16.
// D[m,n] = cn[n] - 2 * R[m,:].cb[n,:]; per-row min -> rowmin (atomicMin).
// ---------------------------------------------------------------------------
__global__ __launch_bounds__(256)
void vq_gemm_approx(const float* __restrict__ R, const float* __restrict__ cb,
                    const float* __restrict__ cn, __nv_bfloat16* __restrict__ D,
                    unsigned* __restrict__ rowmin)
{
    extern __shared__ uint32_t dyn[];
    uint32_t* sA = dyn;
    uint32_t* sB = dyn + PLW;
    unsigned* sMin = (unsigned*)(dyn + 2*PLW);

    const int tid  = threadIdx.x;
    const int lane = tid & 31;
    const int warp = tid >> 5;
    const int wm = warp & 1;
    const int wn = warp >> 1;
    const int m0 = blockIdx.x << 7;
    const int n0 = blockIdx.y << 7;

    float acc[4][4][4];
#pragma unroll
    for (int i = 0; i < 4; i++)
#pragma unroll
        for (int j = 0; j < 4; j++)
#pragma unroll
            for (int k = 0; k < 4; k++) acc[i][j][k] = 0.f;

    if (tid < 128) sMin[tid] = 0xFFFFFFFFu;

    for (int k0 = 0; k0 < 256; k0 += 32) {
#pragma unroll
        for (int i = 0; i < 4; i++) {
            int idx4 = tid + i*256;
            int m  = idx4 >> 3;
            int kq = idx4 & 7;
            int oa = m*33 + kq*4;
            float4 a = *(const float4*)(R  + (size_t)(m0 + m)*256 + k0 + kq*4);
            sA[oa+0] = f2tf(a.x); sA[oa+1] = f2tf(a.y);
            sA[oa+2] = f2tf(a.z); sA[oa+3] = f2tf(a.w);
            float4 b = *(const float4*)(cb + (size_t)(n0 + m)*256 + k0 + kq*4);
            sB[oa+0] = f2tf(b.x); sB[oa+1] = f2tf(b.y);
            sB[oa+2] = f2tf(b.z); sB[oa+3] = f2tf(b.w);
        }
        __syncthreads();

#pragma unroll
        for (int ks = 0; ks < 4; ks++) {
            const int kb = ks*8 + (lane & 3);
            uint32_t bf[4][2];
#pragma unroll
            for (int fn = 0; fn < 4; fn++) {
                int n = wn*32 + fn*8 + (lane >> 2);
                bf[fn][0] = sB[n*33 + kb];  bf[fn][1] = sB[n*33 + kb + 4];
            }
#pragma unroll
            for (int fm = 0; fm < 4; fm++) {
                int r = wm*64 + fm*16 + (lane >> 2);
                uint32_t af[4];
                af[0] = sA[r*33 + kb];     af[1] = sA[(r+8)*33 + kb];
                af[2] = sA[r*33 + kb+4];   af[3] = sA[(r+8)*33 + kb+4];
#pragma unroll
                for (int fn = 0; fn < 4; fn++)
                    mma_tf32(acc[fm][fn], af, bf[fn][0], bf[fn][1]);
            }
        }
        __syncthreads();
    }

    float cnv[4][2];
#pragma unroll
    for (int fn = 0; fn < 4; fn++) {
        int col = n0 + wn*32 + fn*8 + 2*(lane & 3);
        cnv[fn][0] = cn[col];
        cnv[fn][1] = cn[col + 1];
    }
#pragma unroll
    for (int fm = 0; fm < 4; fm++) {
#pragma unroll
        for (int h = 0; h < 2; h++) {
            int rl = wm*64 + fm*16 + (lane >> 2) + h*8;
            int rg = m0 + rl;
            float mn = 3.402823466e38f;
#pragma unroll
            for (int fn = 0; fn < 4; fn++) {
                int col = n0 + wn*32 + fn*8 + 2*(lane & 3);
                float vx = cnv[fn][0] - 2.f*acc[fm][fn][h*2 + 0];
                float vy = cnv[fn][1] - 2.f*acc[fm][fn][h*2 + 1];
                mn = fminf(mn, fminf(vx, vy));
                *(__nv_bfloat162*)(D + (size_t)rg*1024 + col) =
                    __floats2bfloat162_rn(vx, vy);
            }
            atomicMin(&sMin[rl], fenc(mn));
        }
    }
    __syncthreads();
    if (tid < 128) atomicMin(&rowmin[m0 + tid], sMin[tid]);
}

__global__ void init_rowmin_all(unsigned* rowmin) {
    rowmin[blockIdx.x*1024 + threadIdx.x] = 0xFFFFFFFFu;
}

// ---------------------------------------------------------------------------
// Phase B: one warp per token; exact-FFMA rescore of candidates within EPS of
// the approx row-min, lowest-index tie-break, fused vq_update.
// ---------------------------------------------------------------------------
__global__ __launch_bounds__(256)
void vq_select_update(const __nv_bfloat16* __restrict__ D, const float* __restrict__ cb,
                      const float* __restrict__ cn,
                      const unsigned* __restrict__ rowmin,
                      float* __restrict__ resid, float* __restrict__ qsum,
                      float* __restrict__ idx_out, int stage,
                      double* __restrict__ lossAcc)
{
    __shared__ double sLoss[8];
    const int warp = threadIdx.x >> 5;
    const int lane = threadIdx.x & 31;
    const int t = blockIdx.x*8 + warp;

    const __nv_bfloat16* drow = D + (size_t)t*1024;
    const float thr = fdec(rowmin[t]) + 0.03f;

    float4 r0 = *(const float4*)(resid + (size_t)t*256 + lane*8);
    float4 r1 = *(const float4*)(resid + (size_t)t*256 + lane*8 + 4);

    float bestd = 3.402823466e38f;
    int   bestn = 0;
    for (int j0 = 0; j0 < 1024; j0 += 32) {
        float dv = __bfloat162float(drow[j0 + lane]);
        unsigned m = __ballot_sync(0xffffffffu, dv <= thr);
        while (m) {
            int src = __ffs(m) - 1; m &= m - 1;
            int j = j0 + src;
            const float* c = cb + (size_t)j*256;
            float4 c0 = *(const float4*)(c + lane*8);
            float4 c1 = *(const float4*)(c + lane*8 + 4);
            float dot = r0.x*c0.x + r0.y*c0.y + r0.z*c0.z + r0.w*c0.w
                      + r1.x*c1.x + r1.y*c1.y + r1.z*c1.z + r1.w*c1.w;
#pragma unroll
            for (int o = 16; o; o >>= 1)
                dot += __shfl_xor_sync(0xffffffffu, dot, o);
            float de = cn[j] - 2.f*dot;
            if (de < bestd) { bestd = de; bestn = j; }
        }
    }

    const float* q = cb + (size_t)bestn*256;
    float4 q0 = *(const float4*)(q + lane*8);
    float4 q1 = *(const float4*)(q + lane*8 + 4);
    float4 s0 = *(float4*)(qsum + (size_t)t*256 + lane*8);
    float4 s1 = *(float4*)(qsum + (size_t)t*256 + lane*8 + 4);

    float ls = 0.f;
    {
        float d;
        d = q0.x-r0.x; ls += d*d;  d = q0.y-r0.y; ls += d*d;
        d = q0.z-r0.z; ls += d*d;  d = q0.w-r0.w; ls += d*d;
        d = q1.x-r1.x; ls += d*d;  d = q1.y-r1.y; ls += d*d;
        d = q1.z-r1.z; ls += d*d;  d = q1.w-r1.w; ls += d*d;
    }
    s0.x += q0.x; s0.y += q0.y; s0.z += q0.z; s0.w += q0.w;
    s1.x += q1.x; s1.y += q1.y; s1.z += q1.z; s1.w += q1.w;
    r0.x -= q0.x; r0.y -= q0.y; r0.z -= q0.z; r0.w -= q0.w;
    r1.x -= q1.x; r1.y -= q1.y; r1.z -= q1.z; r1.w -= q1.w;
    *(float4*)(qsum  + (size_t)t*256 + lane*8)     = s0;
    *(float4*)(qsum  + (size_t)t*256 + lane*8 + 4) = s1;
    *(float4*)(resid + (size_t)t*256 + lane*8)     = r0;
    *(float4*)(resid + (size_t)t*256 + lane*8 + 4) = r1;

#pragma unroll
    for (int o = 16; o; o >>= 1) ls += __shfl_down_sync(0xffffffffu, ls, o);
    if (lane == 0) {
        sLoss[warp] = (double)ls;
        idx_out[(t >> 12)*16384 + stage*4096 + (t & 4095)] = (float)bestn;
    }
    __syncthreads();
    if (threadIdx.x == 0) {
        double tot = 0.0;
#pragma unroll
        for (int w = 0; w < 8; w++) tot += sLoss[w];
        atomicAdd(lossAcc + stage, tot);
    }
}

// ---------------------------------------------------------------------------
// Implicit-GEMM FFMA conv (3x3 s1 or 4x4 s2, pad 1). Output 64x64 per image.
// Double-buffered smem, register-staged prefetch, SINGLE sync per chunk.
// ---------------------------------------------------------------------------
template<int KSZ, int S>
__global__ __launch_bounds__(256, 2)
void conv_ffma(const float* __restrict__ in, const float* __restrict__ wt,
               const float* __restrict__ bias, float* __restrict__ out,
               int Cin, int Hin, int Win, int Cout, int relu)
{
    __shared__ float sA[2][16*128];
    __shared__ float sB[2][16*128];
    const int tid = threadIdx.x;
    const int tx = tid & 15;
    const int ty = tid >> 4;
    const int m0  = blockIdx.x << 7;
    const int co0 = blockIdx.y << 7;
    const int b   = m0 >> 12;
    const int y0  = (m0 & 4095) >> 6;
    const int cpt = Cin >> 4;
    const int NCH = KSZ*KSZ*cpt;

    float acc[8][8];
#pragma unroll
    for (int i = 0; i < 8; i++)
#pragma unroll
        for (int j = 0; j < 8; j++) acc[i][j] = 0.f;

    float ra[8], rb[8];

    auto loadc = [&](int q) {
        int tap = q / cpt;
        int ci0 = (q - tap*cpt) << 4;
        int dy = tap/KSZ - 1, dx = tap%KSZ - 1;
#pragma unroll
        for (int v = 0; v < 8; v++) {
            int idx = tid + v*256;
            int ci = idx >> 7, pix = idx & 127;
            int iy = (y0 + (pix >> 6))*S + dy;
            int ix = (pix & 63)*S + dx;
            float val = 0.f;
            if ((unsigned)iy < (unsigned)Hin && (unsigned)ix < (unsigned)Win)
                val = in[((size_t)(b*Cin + ci0 + ci)*Hin + iy)*Win + ix];
            ra[v] = val;
            rb[v] = wt[((size_t)tap*Cin + ci0 + ci)*Cout + co0 + pix];
        }
    };
    auto storec = [&](int buf) {
#pragma unroll
        for (int v = 0; v < 8; v++) {
            int idx = tid + v*256;
            int ci = idx >> 7, pix = idx & 127;
            sA[buf][ci*128 + pix] = ra[v];
            sB[buf][ci*128 + pix] = rb[v];
        }
    };

    loadc(0); storec(0); __syncthreads();
    for (int q = 0; q < NCH; q++) {
        if (q + 1 < NCH) loadc(q + 1);
        const float* pA = sA[q & 1];
        const float* pB = sB[q & 1];
#pragma unroll
        for (int kk = 0; kk < 16; kk++) {
            float4 a0 = *(const float4*)&pA[kk*128 + tx*8];
            float4 a1 = *(const float4*)&pA[kk*128 + tx*8 + 4];
            float4 b0 = *(const float4*)&pB[kk*128 + ty*8];
            float4 b1 = *(const float4*)&pB[kk*128 + ty*8 + 4];
            float av[8] = {a0.x,a0.y,a0.z,a0.w,a1.x,a1.y,a1.z,a1.w};
            float bv[8] = {b0.x,b0.y,b0.z,b0.w,b1.x,b1.y,b1.z,b1.w};
#pragma unroll
            for (int i = 0; i < 8; i++)
#pragma unroll
                for (int j = 0; j < 8; j++) acc[i][j] += av[i]*bv[j];
        }
        // store into the buffer NOT being read this iteration; reads of that
        // buffer finished before the previous barrier => one sync suffices.
        if (q + 1 < NCH) storec((q + 1) & 1);
        __syncthreads();
    }

    const int yr = y0 + (tx >> 3);
    const int xc = (tx*8) & 63;
#pragma unroll
    for (int j = 0; j < 8; j++) {
        int co = co0 + ty*8 + j;
        float bv = bias[co];
        float4 v0, v1;
        v0.x = acc[0][j]+bv; v0.y = acc[1][j]+bv; v0.z = acc[2][j]+bv; v0.w = acc[3][j]+bv;
        v1.x = acc[4][j]+bv; v1.y = acc[5][j]+bv; v1.z = acc[6][j]+bv; v1.w = acc[7][j]+bv;
        if (relu) {
            v0.x = fmaxf(v0.x,0.f); v0.y = fmaxf(v0.y,0.f); v0.z = fmaxf(v0.z,0.f); v0.w = fmaxf(v0.w,0.f);
            v1.x = fmaxf(v1.x,0.f); v1.y = fmaxf(v1.y,0.f); v1.z = fmaxf(v1.z,0.f); v1.w = fmaxf(v1.w,0.f);
        }
        float* p = out + ((size_t)(b*Cout + co)*4096 + yr*64 + xc);
        *(float4*)p = v0;
        *(float4*)(p + 4) = v1;
    }
}

// ---------------------------------------------------------------------------
// Implicit-GEMM FFMA convT (k4 s2 p1), parity-decomposed, Cout=64, relu.
// Double-buffered smem, register-staged prefetch, SINGLE sync per chunk.
// ---------------------------------------------------------------------------
__global__ __launch_bounds__(256, 2)
void convT_ffma(const float* __restrict__ in, const float* __restrict__ wtT,
                const float* __restrict__ bias, float* __restrict__ out,
                int Cin, int Hin, int Win, int wsh, int hwsh)
{
    __shared__ float sA[2][16*256];
    __shared__ float sB[2][16*64];
    const int tid = threadIdx.x;
    const int tx = tid & 31;
    const int ty = tid >> 5;
    const int P0 = blockIdx.x << 8;
    const int b   = P0 >> hwsh;
    const int lp  = P0 & ((1 << hwsh) - 1);
    const int my0 = lp >> wsh;
    const int p  = blockIdx.z;
    const int ey = p >> 1, ex = p & 1;
    const float* wtp = wtT + (size_t)p*4*Cin*64;
    const int Wo  = Win*2;
    const int HWo = (Hin*Win)*4;
    const int cpt = Cin >> 4;
    const int NCH = 4*cpt;

    float acc[8][8];
#pragma unroll
    for (int i = 0; i < 8; i++)
#pragma unroll
        for (int j = 0; j < 8; j++) acc[i][j] = 0.f;

    float ra[16], rb[4];

    auto loadc = [&](int q) {
        int t = q / cpt;
        int ci0 = (q - t*cpt) << 4;
        int jy = t >> 1, jx = t & 1;
        int ry = (ey == 0) ? (jy == 0 ? 0 : -1) : (jy == 0 ? 1 : 0);
        int rx = (ex == 0) ? (jx == 0 ? 0 : -1) : (jx == 0 ? 1 : 0);
#pragma unroll
        for (int v = 0; v < 16; v++) {
            int idx = tid + v*256;
            int ci = idx >> 8, pix = idx & 255;
            int iy = my0 + (pix >> wsh) + ry;
            int ix = (pix & (Win-1)) + rx;
            float val = 0.f;
            if ((unsigned)iy < (unsigned)Hin && (unsigned)ix < (unsigned)Win)
                val = in[((size_t)(b*Cin + ci0 + ci)*Hin + iy)*Win + ix];
            ra[v] = val;
        }
#pragma unroll
        for (int v = 0; v < 4; v++) {
            int idx = tid + v*256;
            int ci = idx >> 6, n = idx & 63;
            rb[v] = wtp[((size_t)t*Cin + ci0 + ci)*64 + n];
        }
    };
    auto storec = [&](int buf) {
#pragma unroll
        for (int v = 0; v < 16; v++) {
            int idx = tid + v*256;
            int ci = idx >> 8, pix = idx & 255;
            sA[buf][ci*256 + pix] = ra[v];
        }
#pragma unroll
        for (int v = 0; v < 4; v++) {
            int idx = tid + v*256;
            int ci = idx >> 6, n = idx & 63;
            sB[buf][ci*64 + n] = rb[v];
        }
    };

    loadc(0); storec(0); __syncthreads();
    for (int q = 0; q < NCH; q++) {
        if (q + 1 < NCH) loadc(q + 1);
        const float* pA = sA[q & 1];
        const float* pB = sB[q & 1];
#pragma unroll
        for (int kk = 0; kk < 16; kk++) {
            float4 a0 = *(const float4*)&pA[kk*256 + tx*8];
            float4 a1 = *(const float4*)&pA[kk*256 + tx*8 + 4];
            float4 b0 = *(const float4*)&pB[kk*64 + ty*8];
            float4 b1 = *(const float4*)&pB[kk*64 + ty*8 + 4];
            float av[8] = {a0.x,a0.y,a0.z,a0.w,a1.x,a1.y,a1.z,a1.w};
            float bv[8] = {b0.x,b0.y,b0.z,b0.w,b1.x,b1.y,b1.z,b1.w};
#pragma unroll
            for (int i = 0; i < 8; i++)
#pragma unroll
                for (int j = 0; j < 8; j++) acc[i][j] += av[i]*bv[j];
        }
        if (q + 1 < NCH) storec((q + 1) & 1);
        __syncthreads();
    }

    const int m  = my0 + ((tx*8) >> wsh);
    const int oy = 2*m + ey;
#pragma unroll
    for (int j = 0; j < 8; j++) {
        int co = ty*8 + j;
        float bv = bias[co];
        float* p0 = out + ((size_t)(b*64 + co)*HWo + oy*Wo + ex);
#pragma unroll
        for (int i = 0; i < 8; i++) {
            int mx = (tx*8 + i) & (Win-1);
            p0[2*mx] = fmaxf(acc[i][j] + bv, 0.f);
        }
    }
}

// ---------------------------------------------------------------------------
// convT4 (k4 s2 p1, Cin=64 -> Cout=3, tanh): N=12 GEMM over shared A rows.
// Weights wp[tau(9)][ci(64)][12 pad 16]. Dynamic smem 59904 B.
// ---------------------------------------------------------------------------
__global__ __launch_bounds__(256)
void convT4_ffma(const float* __restrict__ in, const float* __restrict__ wp,
                 const float* __restrict__ bias, float* __restrict__ out)
{
    extern __shared__ float dynf[];
    float* sA = dynf;              // [16 ci][3 rows][264]
    float* sB = dynf + 16*792;     // [9 tau][16 ci][16]

    const int tid = threadIdx.x;
    const int b  = blockIdx.x >> 8;
    const int my = blockIdx.x & 255;
    const float* inb = in + (size_t)b*64*65536;

    float acc[12];
#pragma unroll
    for (int i = 0; i < 12; i++) acc[i] = 0.f;

    for (int ci0 = 0; ci0 < 64; ci0 += 16) {
        for (int idx = tid; idx < 16*3*258; idx += 256) {
            int ci = idx / 774;
            int rem = idx - ci*774;
            int r = rem / 258, c = rem - r*258;
            int iy = my - 1 + r, ix = c - 1;
            float v = 0.f;
            if ((unsigned)iy < 256u && (unsigned)ix < 256u)
                v = inb[((size_t)(ci0 + ci)*256 + iy)*256 + ix];
            sA[ci*792 + r*264 + c] = v;
        }
        for (int idx = tid; idx < 9*16*16; idx += 256) {
            int tau = idx >> 8;
            int rem = idx & 255;
            int ci = rem >> 4, s = rem & 15;
            sB[(tau*16 + ci)*16 + s] = wp[((size_t)tau*64 + ci0 + ci)*16 + s];
        }
        __syncthreads();

        for (int ci = 0; ci < 16; ci++) {
#pragma unroll
            for (int tau = 0; tau < 9; tau++) {
                float a = sA[ci*792 + (tau/3)*264 + (tau%3) + tid];
                const float4* bp = (const float4*)&sB[(tau*16 + ci)*16];
                float4 b0 = bp[0], b1 = bp[1], b2 = bp[2];
                acc[0] += a*b0.x; acc[1]  += a*b0.y; acc[2]  += a*b0.z;
                acc[3] += a*b0.w; acc[4]  += a*b1.x; acc[5]  += a*b1.y;
                acc[6] += a*b1.z; acc[7]  += a*b1.w; acc[8]  += a*b2.x;
                acc[9] += a*b2.y; acc[10] += a*b2.z; acc[11] += a*b2.w;
            }
        }
        __syncthreads();
    }

    const int mx = tid;
#pragma unroll
    for (int p = 0; p < 4; p++) {
        int ey = p >> 1, ex = p & 1;
        int oy = 2*my + ey;
#pragma unroll
        for (int co = 0; co < 3; co++) {
            float v = tanhf(acc[p*3 + co] + bias[co]);
            out[(((size_t)b*3 + co)*512 + oy)*512 + 2*mx + ex] = v;
        }
    }
}

// ---------------------------------------------------------------------------
// Fused weight repack (single launch)
// ---------------------------------------------------------------------------
__device__ __forceinline__ void rp_conv(const float* w, float* wt,
                                        int Cin, int Cout, int KK, int idx)
{
    int co = idx % Cout; int r = idx / Cout;
    int ci = r % Cin;    int tap = r / Cin;
    wt[idx] = w[(co*Cin + ci)*KK + tap];
}

__device__ __forceinline__ void rp_convT(const float* w, float* wtT,
                                         int Cin, int Cout, int idx)
{
    int co = idx % Cout; int r = idx / Cout;
    int ci = r % Cin;    int pt = r / Cin;
    int p = pt >> 2, t = pt & 3;
    int ey = p >> 1, ex = p & 1;
    int jy = t >> 1, jx = t & 1;
    int ky = (ey == 0) ? (jy == 0 ? 1 : 3) : (jy == 0 ? 0 : 2);
    int kx = (ex == 0) ? (jx == 0 ? 1 : 3) : (jx == 0 ? 0 : 2);
    wtT[idx] = w[((ci*Cout + co)*4 + ky)*4 + kx];
}

__device__ __forceinline__ void rp_w4(const float* w, float* wp, int idx)
{
    int tau = idx >> 10;
    int rem = idx & 1023;
    int ci = rem >> 4, s = rem & 15;
    float v = 0.f;
    if (s < 12) {
        int p = s / 3, co = s - p*3;
        int ey = p >> 1, ex = p & 1;
        int dy = tau/3 - 1, dx = tau%3 - 1;
        int ky = -1, kx = -1;
        if (ey == 0) { if (dy == 0) ky = 1; else if (dy == -1) ky = 3; }
        else         { if (dy == 1) ky = 0; else if (dy ==  0) ky = 2; }
        if (ex == 0) { if (dx == 0) kx = 1; else if (dx == -1) kx = 3; }
        else         { if (dx == 1) kx = 0; else if (dx ==  0) kx = 2; }
        if (ky >= 0 && kx >= 0)
            v = w[((ci*3 + co)*4 + ky)*4 + kx];
    }
    wp[idx] = v;
}

__global__ void repack_all(const float* ew2, const float* ew3, const float* ew4,
                           const float* dw1, const float* dw2, const float* dw3,
                           const float* dw4,
                           float* wt_e2, float* wt_e3, float* wt_e4, float* wt_d1,
                           float* wtT_d2, float* wtT_d3, float* w4p)
{
    int idx = blockIdx.x*256 + threadIdx.x;
    if (idx < 131072) { rp_conv(ew2, wt_e2, 64, 128, 16, idx); return; }
    idx -= 131072;
    if (idx < 294912) { rp_conv(ew3, wt_e3, 128, 256, 9, idx); return; }
    idx -= 294912;
    if (idx < 589824) { rp_conv(ew4, wt_e4, 256, 256, 9, idx); return; }
    idx -= 589824;
    if (idx < 294912) { rp_conv(dw1, wt_d1, 256, 128, 9, idx); return; }
    idx -= 294912;
    if (idx < 131072) { rp_convT(dw2, wtT_d2, 128, 64, idx); return; }
    idx -= 131072;
    if (idx < 65536)  { rp_convT(dw3, wtT_d3, 64, 64, idx); return; }
    idx -= 65536;
    if (idx < 9216)   { rp_w4(dw4, w4p, idx); }
}

// ---------------------------------------------------------------------------
// Direct conv (FFMA) — enc1 only (Cin=3).
// ---------------------------------------------------------------------------
template<int K, int S, int CIN_T>
__global__ __launch_bounds__(128)
void conv2d_tiled(const float* __restrict__ in, const float* __restrict__ w,
                  const float* __restrict__ bias, float* __restrict__ out,
                  int Cin, int H, int W, int Cout, int Ho, int Wo,
                  int pad, int relu)
{
    constexpr int IH = 3*S + K;
    constexpr int IW = 15*S + K;
    constexpr int KK = K*K;
    __shared__ __align__(16) float s_in[CIN_T*IH*IW];
    __shared__ __align__(16) float s_w [CIN_T*KK*64];

    const int tid = threadIdx.x;
    const int px  = tid & 15;
    const int cg  = tid >> 4;
    const int hb  = Ho >> 2;
    const int b   = blockIdx.y / hb;
    const int oy0 = (blockIdx.y % hb) * 4;
    const int ox0 = blockIdx.x * 16;
    const int co0 = blockIdx.z * 64;
    const int iy0 = oy0*S - pad;
    const int ix0 = ox0*S - pad;

    float acc[4][8];
#pragma unroll
    for (int p = 0; p < 4; p++)
#pragma unroll
        for (int c = 0; c < 8; c++) acc[p][c] = 0.f;

    for (int ci0 = 0; ci0 < Cin; ci0 += CIN_T) {
        for (int idx = tid; idx < CIN_T*IH*IW; idx += 128) {
            int ci  = idx / (IH*IW);
            int rem = idx % (IH*IW);
            int r   = rem / IW, c = rem % IW;
            int iy  = iy0 + r, ix = ix0 + c;
            float v = 0.f;
            if ((unsigned)iy < (unsigned)H && (unsigned)ix < (unsigned)W &&
                (ci0 + ci) < Cin)
                v = in[((b*Cin + ci0 + ci)*H + iy)*W + ix];
            s_in[idx] = v;
        }
        for (int idx = tid; idx < CIN_T*KK*64; idx += 128) {
            int co  = idx & 63;
            int rem = idx >> 6;
            int kk  = rem % KK;
            int ci  = rem / KK;
            float v = 0.f;
            if ((ci0 + ci) < Cin)
                v = w[((co0 + co)*Cin + ci0 + ci)*KK + kk];
            s_w[idx] = v;
        }
        __syncthreads();

        for (int ci = 0; ci < CIN_T; ci++) {
#pragma unroll
            for (int kh = 0; kh < K; kh++) {
#pragma unroll
                for (int kw = 0; kw < K; kw++) {
                    const float4* wp =
                        (const float4*)(s_w + ((ci*KK + kh*K + kw) << 6) + (cg << 3));
                    float4 w0 = wp[0], w1 = wp[1];
#pragma unroll
                    for (int p = 0; p < 4; p++) {
                        float iv = s_in[(ci*IH + p*S + kh)*IW + px*S + kw];
                        acc[p][0] += iv*w0.x; acc[p][1] += iv*w0.y;
                        acc[p][2] += iv*w0.z; acc[p][3] += iv*w0.w;
                        acc[p][4] += iv*w1.x; acc[p][5] += iv*w1.y;
                        acc[p][6] += iv*w1.z; acc[p][7] += iv*w1.w;
                    }
                }
            }
        }
        __syncthreads();
    }

#pragma unroll
    for (int c = 0; c < 8; c++) {
        int co = co0 + (cg << 3) + c;
        float bv = bias[co];
#pragma unroll
        for (int p = 0; p < 4; p++) {
            float v = acc[p][c] + bv;
            if (relu) v = fmaxf(v, 0.f);
            out[((b*Cout + co)*Ho + oy0 + p)*Wo + ox0 + px] = v;
        }
    }
}

// ---------------------------------------------------------------------------
// Helpers
// ---------------------------------------------------------------------------
__global__ void cnorm_kernel(const float* __restrict__ cb, float* __restrict__ cn) {
    int row  = (blockIdx.x*blockDim.x + threadIdx.x) >> 5;
    int lane = threadIdx.x & 31;
    if (row >= 4096) return;
    const float* p = cb + (size_t)row*256;
    float s = 0.f;
    for (int c = lane; c < 256; c += 32) { float v = p[c]; s += v*v; }
#pragma unroll
    for (int o = 16; o; o >>= 1) s += __shfl_down_sync(0xffffffffu, s, o);
    if (!lane) cn[row] = s;
}

__global__ void zero_loss(double* l) { if (threadIdx.x < 4) l[threadIdx.x] = 0.0; }

__global__ void write_loss(const double* __restrict__ l, float* __restrict__ o) {
    if (threadIdx.x < 4)
        o[threadIdx.x] = (float)(l[threadIdx.x] * (1.0/(65536.0*256.0)));
}

__global__ void z_to_tokens(const float* __restrict__ z,
                            float* __restrict__ resid, float* __restrict__ qsum)
{
    __shared__ float t[32][33];
    int b  = blockIdx.z;
    int s0 = blockIdx.x*32;
    int c0 = blockIdx.y*32;
    int x  = threadIdx.x;
    for (int y = threadIdx.y; y < 32; y += 8)
        t[y][x] = z[((size_t)b*256 + c0 + y)*4096 + s0 + x];
    __syncthreads();
    for (int y = threadIdx.y; y < 32; y += 8) {
        size_t o = ((size_t)b*4096 + s0 + y)*256 + c0 + x;
        resid[o] = t[x][y];
        qsum[o]  = 0.f;
    }
}

__global__ void tokens_to_z(const float* __restrict__ qsum,
                            float* __restrict__ z1, float* __restrict__ z2)
{
    __shared__ float t[32][33];
    int b  = blockIdx.z;
    int c0 = blockIdx.x*32;
    int s0 = blockIdx.y*32;
    int x  = threadIdx.x;
    for (int y = threadIdx.y; y < 32; y += 8)
        t[y][x] = qsum[((size_t)b*4096 + s0 + y)*256 + c0 + x];
    __syncthreads();
    for (int y = threadIdx.y; y < 32; y += 8) {
        float v = t[x][y];
        size_t o = ((size_t)b*256 + c0 + y)*4096 + s0 + x;
        z1[o] = v; z2[o] = v;
    }
}

// ---------------------------------------------------------------------------
// Launch
// ---------------------------------------------------------------------------
extern "C" void kernel_launch(void* const* d_in, const int* in_sizes, int n_in,
                              void* d_out, int out_size)
{
    const float* x   = (const float*)d_in[0];
    const float* ew1 = (const float*)d_in[1];  const float* eb1 = (const float*)d_in[2];
    const float* ew2 = (const float*)d_in[3];  const float* eb2 = (const float*)d_in[4];
    const float* ew3 = (const float*)d_in[5];  const float* eb3 = (const float*)d_in[6];
    const float* ew4 = (const float*)d_in[7];  const float* eb4 = (const float*)d_in[8];
    const float* cbs = (const float*)d_in[9];
    const float* dw1 = (const float*)d_in[10]; const float* db1 = (const float*)d_in[11];
    const float* dw2 = (const float*)d_in[12]; const float* db2 = (const float*)d_in[13];
    const float* dw3 = (const float*)d_in[14]; const float* db3 = (const float*)d_in[15];
    const float* dw4 = (const float*)d_in[16]; const float* db4 = (const float*)d_in[17];
    float* out = (float*)d_out;

    float *h1, *h2, *h3, *z, *resid, *qsum, *cnorm, *w4p, *wt, *wtT, *d3;
    double* loss; unsigned* rowmin;
    cudaGetSymbolAddress((void**)&h1,    g_h1);
    cudaGetSymbolAddress((void**)&h2,    g_h2);
    cudaGetSymbolAddress((void**)&h3,    g_h3);
    cudaGetSymbolAddress((void**)&z,     g_z);
    cudaGetSymbolAddress((void**)&resid, g_resid);
    cudaGetSymbolAddress((void**)&qsum,  g_qsum);
    cudaGetSymbolAddress((void**)&loss,  g_loss);
    cudaGetSymbolAddress((void**)&cnorm, g_cnorm);
    cudaGetSymbolAddress((void**)&rowmin,g_rowmin);
    cudaGetSymbolAddress((void**)&w4p,   g_w4p);
    cudaGetSymbolAddress((void**)&wt,    g_wt);
    cudaGetSymbolAddress((void**)&wtT,   g_wtT);
    cudaGetSymbolAddress((void**)&d3,    g_d3);

    float* wt_e2  = wt;                               // 16*64*128  = 131072
    float* wt_e3  = wt + 131072;                      // 9*128*256  = 294912
    float* wt_e4  = wt + 131072 + 294912;             // 9*256*256  = 589824
    float* wt_d1  = wt + 131072 + 294912 + 589824;    // 9*256*128  = 294912
    float* wtT_d2 = wtT;                              // 16*128*64  = 131072
    float* wtT_d3 = wtT + 131072;                     // 16*64*64   = 65536

    // output layout: recon | indices | commit_loss | quantized
    float* recO   = out;
    float* idxO   = out + 12582912;
    float* lossO  = idxO + 262144;
    float* quantO = lossO + 4;

    const int PA_SMEM  = 2*PLW*4 + 512;               // 34304
    const int CT4_SMEM = (16*792 + 9*16*16)*4;        // 59904
    cudaFuncSetAttribute(vq_gemm_approx, cudaFuncAttributeMaxDynamicSharedMemorySize, PA_SMEM);
    cudaFuncSetAttribute(convT4_ffma,    cudaFuncAttributeMaxDynamicSharedMemorySize, CT4_SMEM);

    // prep
    repack_all     <<<5924, 256>>>(ew2, ew3, ew4, dw1, dw2, dw3, dw4,
                                   wt_e2, wt_e3, wt_e4, wt_d1, wtT_d2, wtT_d3, w4p);
    cnorm_kernel   <<<512, 256>>>(cbs, cnorm);
    zero_loss      <<<1, 32>>>(loss);
    init_rowmin_all<<<256, 1024>>>(rowmin);

    // ---- encoder (exact fp32) ----
    conv2d_tiled<4,2,4><<<dim3(8, 32*16, 1), 128>>>(x, ew1, eb1, h1, 3, 256, 256, 64, 128, 128, 1, 1);
    conv_ffma<4,2><<<dim3(512, 1), 256>>>(h1, wt_e2, eb2, h2,  64, 128, 128, 128, 1);
    conv_ffma<3,1><<<dim3(512, 2), 256>>>(h2, wt_e3, eb3, h3, 128,  64,  64, 256, 1);
    conv_ffma<3,1><<<dim3(512, 2), 256>>>(h3, wt_e4, eb4, z,  256,  64,  64, 256, 0);

    // ---- residual VQ: single-MMA tf32 approx distances (bf16 D) + exact rescore ----
    z_to_tokens<<<dim3(128, 8, 16), dim3(32, 8)>>>(z, resid, qsum);
    __nv_bfloat16* Dh = (__nv_bfloat16*)d3;
    for (int s = 0; s < 4; s++) {
        vq_gemm_approx  <<<dim3(512, 8), 256, PA_SMEM>>>(resid, cbs + (size_t)s*1024*256,
                                                         cnorm + s*1024, Dh, rowmin + s*65536);
        vq_select_update<<<8192, 256>>>(Dh, cbs + (size_t)s*1024*256, cnorm + s*1024,
                                        rowmin + s*65536, resid, qsum, idxO, s, loss);
    }
    write_loss <<<1, 32>>>(loss, lossO);
    tokens_to_z<<<dim3(8, 128, 16), dim3(32, 8)>>>(qsum, z, quantO);

    // ---- decoder (FFMA, exact) ----
    conv_ffma<3,1><<<dim3(512, 1), 256>>>(z, wt_d1, db1, h2, 256, 64, 64, 128, 1);
    convT_ffma<<<dim3( 256, 1, 4), 256>>>(h2, wtT_d2, db2, h1, 128,  64,  64, 6, 12);
    convT_ffma<<<dim3(1024, 1, 4), 256>>>(h1, wtT_d3, db3, d3,  64, 128, 128, 7, 14);
    convT4_ffma<<<4096, 256, CT4_SMEM>>>(d3, w4p, db4, recO);
}

// round 12
// speedup vs baseline: 1.1532x; 1.0207x over previous
#include <cuda_runtime.h>
#include <cuda_bf16.h>
#include <cstdint>

// ---------------------------------------------------------------------------
// Scratch (device globals — no allocation allowed)
// ---------------------------------------------------------------------------
__device__ float g_h1[16*64*128*128];          // enc1 out / dec2 out (reused)
__device__ float g_h2[16*128*64*64];           // enc2 out / dec1 out (reused)
__device__ float g_h3[16*256*64*64];           // enc3 out
__device__ float g_z [16*256*64*64];           // enc4 out (z) / quantized NCHW (reused)
__device__ float g_resid[65536*256];
__device__ float g_qsum [65536*256];
__device__ double g_loss[4];
__device__ float g_cnorm[4*1024];
__device__ unsigned g_rowmin[4*65536];
__device__ float g_w4p[9*64*16];               // dec_w4 repacked [tau][ci][12 pad 16]
__device__ float g_wt[1310720];                // conv weights repacked [tap][ci][co]
__device__ float g_wtT[196608];                // convT weights [parity][tap][ci][co]
__device__ float g_d3[16*64*256*256];          // dec3 out; ALSO the 65536x1024 D (bf16)

// ---------------------------------------------------------------------------
// tf32 helpers (approximate Phase-A path only; correctness never depends on it)
// ---------------------------------------------------------------------------
__device__ __forceinline__ uint32_t f2tf(float f) {
    uint32_t u;
    asm("cvt.rna.tf32.f32 %0, %1;" : "=r"(u) : "f"(f));
    return u;
}

__device__ __forceinline__ void mma_tf32(float* c, const uint32_t* a,
                                         uint32_t b0, uint32_t b1) {
    asm volatile(
        "mma.sync.aligned.m16n8k8.row.col.f32.tf32.tf32.f32 "
        "{%0,%1,%2,%3},{%4,%5,%6,%7},{%8,%9},{%0,%1,%2,%3};"
        : "+f"(c[0]), "+f"(c[1]), "+f"(c[2]), "+f"(c[3])
        : "r"(a[0]), "r"(a[1]), "r"(a[2]), "r"(a[3]), "r"(b0), "r"(b1));
}

// order-preserving float <-> uint32 (for atomicMin)
__device__ __forceinline__ unsigned fenc(float d) {
    unsigned u = __float_as_uint(d);
    return (u & 0x80000000u) ? ~u : (u | 0x80000000u);
}
__device__ __forceinline__ float fdec(unsigned e) {
    unsigned u = (e & 0x80000000u) ? (e & 0x7FFFFFFFu) : ~e;
    return __uint_as_float(u);
}

static const int PLW = 128*33;   // one smem plane in words (stride 33: conflict-free)

// ---------------------------------------------------------------------------
// Phase A: approximate distance matrix, single tf32 MMA, D stored as bf16.
// D[m,n] = cn[n] - 2 * R[m,:].cb[n,:]; per-row min -> rowmin (atomicMin).
// ---------------------------------------------------------------------------
__global__ __launch_bounds__(256)
void vq_gemm_approx(const float* __restrict__ R, const float* __restrict__ cb,
                    const float* __restrict__ cn, __nv_bfloat16* __restrict__ D,
                    unsigned* __restrict__ rowmin)
{
    extern __shared__ uint32_t dyn[];
    uint32_t* sA = dyn;
    uint32_t* sB = dyn + PLW;
    unsigned* sMin = (unsigned*)(dyn + 2*PLW);

    const int tid  = threadIdx.x;
    const int lane = tid & 31;
    const int warp = tid >> 5;
    const int wm = warp & 1;
    const int wn = warp >> 1;
    const int m0 = blockIdx.x << 7;
    const int n0 = blockIdx.y << 7;

    float acc[4][4][4];
#pragma unroll
    for (int i = 0; i < 4; i++)
#pragma unroll
        for (int j = 0; j < 4; j++)
#pragma unroll
            for (int k = 0; k < 4; k++) acc[i][j][k] = 0.f;

    if (tid < 128) sMin[tid] = 0xFFFFFFFFu;

    for (int k0 = 0; k0 < 256; k0 += 32) {
#pragma unroll
        for (int i = 0; i < 4; i++) {
            int idx4 = tid + i*256;
            int m  = idx4 >> 3;
            int kq = idx4 & 7;
            int oa = m*33 + kq*4;
            float4 a = *(const float4*)(R  + (size_t)(m0 + m)*256 + k0 + kq*4);
            sA[oa+0] = f2tf(a.x); sA[oa+1] = f2tf(a.y);
            sA[oa+2] = f2tf(a.z); sA[oa+3] = f2tf(a.w);
            float4 b = *(const float4*)(cb + (size_t)(n0 + m)*256 + k0 + kq*4);
            sB[oa+0] = f2tf(b.x); sB[oa+1] = f2tf(b.y);
            sB[oa+2] = f2tf(b.z); sB[oa+3] = f2tf(b.w);
        }
        __syncthreads();

#pragma unroll
        for (int ks = 0; ks < 4; ks++) {
            const int kb = ks*8 + (lane & 3);
            uint32_t bf[4][2];
#pragma unroll
            for (int fn = 0; fn < 4; fn++) {
                int n = wn*32 + fn*8 + (lane >> 2);
                bf[fn][0] = sB[n*33 + kb];  bf[fn][1] = sB[n*33 + kb + 4];
            }
#pragma unroll
            for (int fm = 0; fm < 4; fm++) {
                int r = wm*64 + fm*16 + (lane >> 2);
                uint32_t af[4];
                af[0] = sA[r*33 + kb];     af[1] = sA[(r+8)*33 + kb];
                af[2] = sA[r*33 + kb+4];   af[3] = sA[(r+8)*33 + kb+4];
#pragma unroll
                for (int fn = 0; fn < 4; fn++)
                    mma_tf32(acc[fm][fn], af, bf[fn][0], bf[fn][1]);
            }
        }
        __syncthreads();
    }

    float cnv[4][2];
#pragma unroll
    for (int fn = 0; fn < 4; fn++) {
        int col = n0 + wn*32 + fn*8 + 2*(lane & 3);
        cnv[fn][0] = cn[col];
        cnv[fn][1] = cn[col + 1];
    }
#pragma unroll
    for (int fm = 0; fm < 4; fm++) {
#pragma unroll
        for (int h = 0; h < 2; h++) {
            int rl = wm*64 + fm*16 + (lane >> 2) + h*8;
            int rg = m0 + rl;
            float mn = 3.402823466e38f;
#pragma unroll
            for (int fn = 0; fn < 4; fn++) {
                int col = n0 + wn*32 + fn*8 + 2*(lane & 3);
                float vx = cnv[fn][0] - 2.f*acc[fm][fn][h*2 + 0];
                float vy = cnv[fn][1] - 2.f*acc[fm][fn][h*2 + 1];
                mn = fminf(mn, fminf(vx, vy));
                *(__nv_bfloat162*)(D + (size_t)rg*1024 + col) =
                    __floats2bfloat162_rn(vx, vy);
            }
            atomicMin(&sMin[rl], fenc(mn));
        }
    }
    __syncthreads();
    if (tid < 128) atomicMin(&rowmin[m0 + tid], sMin[tid]);
}

__global__ void init_rowmin_all(unsigned* rowmin) {
    rowmin[blockIdx.x*1024 + threadIdx.x] = 0xFFFFFFFFu;
}

// ---------------------------------------------------------------------------
// Phase B: one warp per token; exact-FFMA rescore of candidates within EPS of
// the approx row-min, lowest-index tie-break, fused vq_update.
// ---------------------------------------------------------------------------
__global__ __launch_bounds__(256)
void vq_select_update(const __nv_bfloat16* __restrict__ D, const float* __restrict__ cb,
                      const float* __restrict__ cn,
                      const unsigned* __restrict__ rowmin,
                      float* __restrict__ resid, float* __restrict__ qsum,
                      float* __restrict__ idx_out, int stage,
                      double* __restrict__ lossAcc)
{
    __shared__ double sLoss[8];
    const int warp = threadIdx.x >> 5;
    const int lane = threadIdx.x & 31;
    const int t = blockIdx.x*8 + warp;

    const __nv_bfloat16* drow = D + (size_t)t*1024;
    const float thr = fdec(rowmin[t]) + 0.03f;

    float4 r0 = *(const float4*)(resid + (size_t)t*256 + lane*8);
    float4 r1 = *(const float4*)(resid + (size_t)t*256 + lane*8 + 4);

    float bestd = 3.402823466e38f;
    int   bestn = 0;
    for (int j0 = 0; j0 < 1024; j0 += 32) {
        float dv = __bfloat162float(drow[j0 + lane]);
        unsigned m = __ballot_sync(0xffffffffu, dv <= thr);
        while (m) {
            int src = __ffs(m) - 1; m &= m - 1;
            int j = j0 + src;
            const float* c = cb + (size_t)j*256;
            float4 c0 = *(const float4*)(c + lane*8);
            float4 c1 = *(const float4*)(c + lane*8 + 4);
            float dot = r0.x*c0.x + r0.y*c0.y + r0.z*c0.z + r0.w*c0.w
                      + r1.x*c1.x + r1.y*c1.y + r1.z*c1.z + r1.w*c1.w;
#pragma unroll
            for (int o = 16; o; o >>= 1)
                dot += __shfl_xor_sync(0xffffffffu, dot, o);
            float de = cn[j] - 2.f*dot;
            if (de < bestd) { bestd = de; bestn = j; }
        }
    }

    const float* q = cb + (size_t)bestn*256;
    float4 q0 = *(const float4*)(q + lane*8);
    float4 q1 = *(const float4*)(q + lane*8 + 4);
    float4 s0 = *(float4*)(qsum + (size_t)t*256 + lane*8);
    float4 s1 = *(float4*)(qsum + (size_t)t*256 + lane*8 + 4);

    float ls = 0.f;
    {
        float d;
        d = q0.x-r0.x; ls += d*d;  d = q0.y-r0.y; ls += d*d;
        d = q0.z-r0.z; ls += d*d;  d = q0.w-r0.w; ls += d*d;
        d = q1.x-r1.x; ls += d*d;  d = q1.y-r1.y; ls += d*d;
        d = q1.z-r1.z; ls += d*d;  d = q1.w-r1.w; ls += d*d;
    }
    s0.x += q0.x; s0.y += q0.y; s0.z += q0.z; s0.w += q0.w;
    s1.x += q1.x; s1.y += q1.y; s1.z += q1.z; s1.w += q1.w;
    r0.x -= q0.x; r0.y -= q0.y; r0.z -= q0.z; r0.w -= q0.w;
    r1.x -= q1.x; r1.y -= q1.y; r1.z -= q1.z; r1.w -= q1.w;
    *(float4*)(qsum  + (size_t)t*256 + lane*8)     = s0;
    *(float4*)(qsum  + (size_t)t*256 + lane*8 + 4) = s1;
    *(float4*)(resid + (size_t)t*256 + lane*8)     = r0;
    *(float4*)(resid + (size_t)t*256 + lane*8 + 4) = r1;

#pragma unroll
    for (int o = 16; o; o >>= 1) ls += __shfl_down_sync(0xffffffffu, ls, o);
    if (lane == 0) {
        sLoss[warp] = (double)ls;
        idx_out[(t >> 12)*16384 + stage*4096 + (t & 4095)] = (float)bestn;
    }
    __syncthreads();
    if (threadIdx.x == 0) {
        double tot = 0.0;
#pragma unroll
        for (int w = 0; w < 8; w++) tot += sLoss[w];
        atomicAdd(lossAcc + stage, tot);
    }
}

// ---------------------------------------------------------------------------
// Implicit-GEMM FFMA conv (3x3 s1 or 4x4 s2, pad 1). Output 64x64 per image.
// Double-buffered smem, register-staged prefetch, single sync per chunk.
// ---------------------------------------------------------------------------
template<int KSZ, int S>
__global__ __launch_bounds__(256, 2)
void conv_ffma(const float* __restrict__ in, const float* __restrict__ wt,
               const float* __restrict__ bias, float* __restrict__ out,
               int Cin, int Hin, int Win, int Cout, int relu)
{
    __shared__ float sA[2][16*128];
    __shared__ float sB[2][16*128];
    const int tid = threadIdx.x;
    const int tx = tid & 15;
    const int ty = tid >> 4;
    const int m0  = blockIdx.x << 7;
    const int co0 = blockIdx.y << 7;
    const int b   = m0 >> 12;
    const int y0  = (m0 & 4095) >> 6;
    const int cpt = Cin >> 4;
    const int NCH = KSZ*KSZ*cpt;

    float acc[8][8];
#pragma unroll
    for (int i = 0; i < 8; i++)
#pragma unroll
        for (int j = 0; j < 8; j++) acc[i][j] = 0.f;

    float ra[8], rb[8];

    auto loadc = [&](int q) {
        int tap = q / cpt;
        int ci0 = (q - tap*cpt) << 4;
        int dy = tap/KSZ - 1, dx = tap%KSZ - 1;
#pragma unroll
        for (int v = 0; v < 8; v++) {
            int idx = tid + v*256;
            int ci = idx >> 7, pix = idx & 127;
            int iy = (y0 + (pix >> 6))*S + dy;
            int ix = (pix & 63)*S + dx;
            float val = 0.f;
            if ((unsigned)iy < (unsigned)Hin && (unsigned)ix < (unsigned)Win)
                val = in[((size_t)(b*Cin + ci0 + ci)*Hin + iy)*Win + ix];
            ra[v] = val;
            rb[v] = wt[((size_t)tap*Cin + ci0 + ci)*Cout + co0 + pix];
        }
    };
    auto storec = [&](int buf) {
#pragma unroll
        for (int v = 0; v < 8; v++) {
            int idx = tid + v*256;
            int ci = idx >> 7, pix = idx & 127;
            sA[buf][ci*128 + pix] = ra[v];
            sB[buf][ci*128 + pix] = rb[v];
        }
    };

    loadc(0); storec(0); __syncthreads();
    for (int q = 0; q < NCH; q++) {
        if (q + 1 < NCH) loadc(q + 1);
        const float* pA = sA[q & 1];
        const float* pB = sB[q & 1];
#pragma unroll
        for (int kk = 0; kk < 16; kk++) {
            float4 a0 = *(const float4*)&pA[kk*128 + tx*8];
            float4 a1 = *(const float4*)&pA[kk*128 + tx*8 + 4];
            float4 b0 = *(const float4*)&pB[kk*128 + ty*8];
            float4 b1 = *(const float4*)&pB[kk*128 + ty*8 + 4];
            float av[8] = {a0.x,a0.y,a0.z,a0.w,a1.x,a1.y,a1.z,a1.w};
            float bv[8] = {b0.x,b0.y,b0.z,b0.w,b1.x,b1.y,b1.z,b1.w};
#pragma unroll
            for (int i = 0; i < 8; i++)
#pragma unroll
                for (int j = 0; j < 8; j++) acc[i][j] += av[i]*bv[j];
        }
        if (q + 1 < NCH) storec((q + 1) & 1);
        __syncthreads();
    }

    const int yr = y0 + (tx >> 3);
    const int xc = (tx*8) & 63;
#pragma unroll
    for (int j = 0; j < 8; j++) {
        int co = co0 + ty*8 + j;
        float bv = bias[co];
        float4 v0, v1;
        v0.x = acc[0][j]+bv; v0.y = acc[1][j]+bv; v0.z = acc[2][j]+bv; v0.w = acc[3][j]+bv;
        v1.x = acc[4][j]+bv; v1.y = acc[5][j]+bv; v1.z = acc[6][j]+bv; v1.w = acc[7][j]+bv;
        if (relu) {
            v0.x = fmaxf(v0.x,0.f); v0.y = fmaxf(v0.y,0.f); v0.z = fmaxf(v0.z,0.f); v0.w = fmaxf(v0.w,0.f);
            v1.x = fmaxf(v1.x,0.f); v1.y = fmaxf(v1.y,0.f); v1.z = fmaxf(v1.z,0.f); v1.w = fmaxf(v1.w,0.f);
        }
        float* p = out + ((size_t)(b*Cout + co)*4096 + yr*64 + xc);
        *(float4*)p = v0;
        *(float4*)(p + 4) = v1;
    }
}

// ---------------------------------------------------------------------------
// Implicit-GEMM FFMA convT (k4 s2 p1), parity-decomposed, Cout=64, relu.
// Pixel mapping mx = tx + 32*i: per-STG lanes hit consecutive even columns
// (50% sector efficiency vs 12.5% with the blocked map). A-fragments become
// scalar LDS (conflict-free: 32 consecutive words).
// ---------------------------------------------------------------------------
__global__ __launch_bounds__(256, 2)
void convT_ffma(const float* __restrict__ in, const float* __restrict__ wtT,
                const float* __restrict__ bias, float* __restrict__ out,
                int Cin, int Hin, int Win, int wsh, int hwsh)
{
    __shared__ float sA[2][16*256];
    __shared__ float sB[2][16*64];
    const int tid = threadIdx.x;
    const int tx = tid & 31;
    const int ty = tid >> 5;
    const int P0 = blockIdx.x << 8;
    const int b   = P0 >> hwsh;
    const int lp  = P0 & ((1 << hwsh) - 1);
    const int my0 = lp >> wsh;
    const int p  = blockIdx.z;
    const int ey = p >> 1, ex = p & 1;
    const float* wtp = wtT + (size_t)p*4*Cin*64;
    const int Wo  = Win*2;
    const int HWo = (Hin*Win)*4;
    const int cpt = Cin >> 4;
    const int NCH = 4*cpt;

    float acc[8][8];
#pragma unroll
    for (int i = 0; i < 8; i++)
#pragma unroll
        for (int j = 0; j < 8; j++) acc[i][j] = 0.f;

    float ra[16], rb[4];

    auto loadc = [&](int q) {
        int t = q / cpt;
        int ci0 = (q - t*cpt) << 4;
        int jy = t >> 1, jx = t & 1;
        int ry = (ey == 0) ? (jy == 0 ? 0 : -1) : (jy == 0 ? 1 : 0);
        int rx = (ex == 0) ? (jx == 0 ? 0 : -1) : (jx == 0 ? 1 : 0);
#pragma unroll
        for (int v = 0; v < 16; v++) {
            int idx = tid + v*256;
            int ci = idx >> 8, pix = idx & 255;
            int iy = my0 + (pix >> wsh) + ry;
            int ix = (pix & (Win-1)) + rx;
            float val = 0.f;
            if ((unsigned)iy < (unsigned)Hin && (unsigned)ix < (unsigned)Win)
                val = in[((size_t)(b*Cin + ci0 + ci)*Hin + iy)*Win + ix];
            ra[v] = val;
        }
#pragma unroll
        for (int v = 0; v < 4; v++) {
            int idx = tid + v*256;
            int ci = idx >> 6, n = idx & 63;
            rb[v] = wtp[((size_t)t*Cin + ci0 + ci)*64 + n];
        }
    };
    auto storec = [&](int buf) {
#pragma unroll
        for (int v = 0; v < 16; v++) {
            int idx = tid + v*256;
            int ci = idx >> 8, pix = idx & 255;
            sA[buf][ci*256 + pix] = ra[v];
        }
#pragma unroll
        for (int v = 0; v < 4; v++) {
            int idx = tid + v*256;
            int ci = idx >> 6, n = idx & 63;
            sB[buf][ci*64 + n] = rb[v];
        }
    };

    loadc(0); storec(0); __syncthreads();
    for (int q = 0; q < NCH; q++) {
        if (q + 1 < NCH) loadc(q + 1);
        const float* pA = sA[q & 1];
        const float* pB = sB[q & 1];
#pragma unroll
        for (int kk = 0; kk < 16; kk++) {
            float av[8];
#pragma unroll
            for (int i = 0; i < 8; i++)
                av[i] = pA[kk*256 + tx + 32*i];
            float4 b0 = *(const float4*)&pB[kk*64 + ty*8];
            float4 b1 = *(const float4*)&pB[kk*64 + ty*8 + 4];
            float bv[8] = {b0.x,b0.y,b0.z,b0.w,b1.x,b1.y,b1.z,b1.w};
#pragma unroll
            for (int i = 0; i < 8; i++)
#pragma unroll
                for (int j = 0; j < 8; j++) acc[i][j] += av[i]*bv[j];
        }
        if (q + 1 < NCH) storec((q + 1) & 1);
        __syncthreads();
    }

    // epilogue: per-STG, lanes write consecutive even columns of one row
#pragma unroll
    for (int j = 0; j < 8; j++) {
        int co = ty*8 + j;
        float bv = bias[co];
        float* pb = out + (size_t)(b*64 + co)*HWo + ex;
#pragma unroll
        for (int i = 0; i < 8; i++) {
            int gp = lp + tx + 32*i;
            int my = gp >> wsh;
            int mx = gp & (Win-1);
            int oy = 2*my + ey;
            pb[oy*Wo + 2*mx] = fmaxf(acc[i][j] + bv, 0.f);
        }
    }
}

// ---------------------------------------------------------------------------
// convT4 (k4 s2 p1, Cin=64 -> Cout=3, tanh): N=12 GEMM over shared A rows.
// Weights wp[tau(9)][ci(64)][12 pad 16]. Dynamic smem 59904 B.
// ---------------------------------------------------------------------------
__global__ __launch_bounds__(256)
void convT4_ffma(const float* __restrict__ in, const float* __restrict__ wp,
                 const float* __restrict__ bias, float* __restrict__ out)
{
    extern __shared__ float dynf[];
    float* sA = dynf;              // [16 ci][3 rows][264]
    float* sB = dynf + 16*792;     // [9 tau][16 ci][16]

    const int tid = threadIdx.x;
    const int b  = blockIdx.x >> 8;
    const int my = blockIdx.x & 255;
    const float* inb = in + (size_t)b*64*65536;

    float acc[12];
#pragma unroll
    for (int i = 0; i < 12; i++) acc[i] = 0.f;

    for (int ci0 = 0; ci0 < 64; ci0 += 16) {
        for (int idx = tid; idx < 16*3*258; idx += 256) {
            int ci = idx / 774;
            int rem = idx - ci*774;
            int r = rem / 258, c = rem - r*258;
            int iy = my - 1 + r, ix = c - 1;
            float v = 0.f;
            if ((unsigned)iy < 256u && (unsigned)ix < 256u)
                v = inb[((size_t)(ci0 + ci)*256 + iy)*256 + ix];
            sA[ci*792 + r*264 + c] = v;
        }
        for (int idx = tid; idx < 9*16*16; idx += 256) {
            int tau = idx >> 8;
            int rem = idx & 255;
            int ci = rem >> 4, s = rem & 15;
            sB[(tau*16 + ci)*16 + s] = wp[((size_t)tau*64 + ci0 + ci)*16 + s];
        }
        __syncthreads();

        for (int ci = 0; ci < 16; ci++) {
#pragma unroll
            for (int tau = 0; tau < 9; tau++) {
                float a = sA[ci*792 + (tau/3)*264 + (tau%3) + tid];
                const float4* bp = (const float4*)&sB[(tau*16 + ci)*16];
                float4 b0 = bp[0], b1 = bp[1], b2 = bp[2];
                acc[0] += a*b0.x; acc[1]  += a*b0.y; acc[2]  += a*b0.z;
                acc[3] += a*b0.w; acc[4]  += a*b1.x; acc[5]  += a*b1.y;
                acc[6] += a*b1.z; acc[7]  += a*b1.w; acc[8]  += a*b2.x;
                acc[9] += a*b2.y; acc[10] += a*b2.z; acc[11] += a*b2.w;
            }
        }
        __syncthreads();
    }

    const int mx = tid;
#pragma unroll
    for (int p = 0; p < 4; p++) {
        int ey = p >> 1, ex = p & 1;
        int oy = 2*my + ey;
#pragma unroll
        for (int co = 0; co < 3; co++) {
            float v = tanhf(acc[p*3 + co] + bias[co]);
            out[(((size_t)b*3 + co)*512 + oy)*512 + 2*mx + ex] = v;
        }
    }
}

// ---------------------------------------------------------------------------
// Fused weight repack (single launch)
// ---------------------------------------------------------------------------
__device__ __forceinline__ void rp_conv(const float* w, float* wt,
                                        int Cin, int Cout, int KK, int idx)
{
    int co = idx % Cout; int r = idx / Cout;
    int ci = r % Cin;    int tap = r / Cin;
    wt[idx] = w[(co*Cin + ci)*KK + tap];
}

__device__ __forceinline__ void rp_convT(const float* w, float* wtT,
                                         int Cin, int Cout, int idx)
{
    int co = idx % Cout; int r = idx / Cout;
    int ci = r % Cin;    int pt = r / Cin;
    int p = pt >> 2, t = pt & 3;
    int ey = p >> 1, ex = p & 1;
    int jy = t >> 1, jx = t & 1;
    int ky = (ey == 0) ? (jy == 0 ? 1 : 3) : (jy == 0 ? 0 : 2);
    int kx = (ex == 0) ? (jx == 0 ? 1 : 3) : (jx == 0 ? 0 : 2);
    wtT[idx] = w[((ci*Cout + co)*4 + ky)*4 + kx];
}

__device__ __forceinline__ void rp_w4(const float* w, float* wp, int idx)
{
    int tau = idx >> 10;
    int rem = idx & 1023;
    int ci = rem >> 4, s = rem & 15;
    float v = 0.f;
    if (s < 12) {
        int p = s / 3, co = s - p*3;
        int ey = p >> 1, ex = p & 1;
        int dy = tau/3 - 1, dx = tau%3 - 1;
        int ky = -1, kx = -1;
        if (ey == 0) { if (dy == 0) ky = 1; else if (dy == -1) ky = 3; }
        else         { if (dy == 1) ky = 0; else if (dy ==  0) ky = 2; }
        if (ex == 0) { if (dx == 0) kx = 1; else if (dx == -1) kx = 3; }
        else         { if (dx == 1) kx = 0; else if (dx ==  0) kx = 2; }
        if (ky >= 0 && kx >= 0)
            v = w[((ci*3 + co)*4 + ky)*4 + kx];
    }
    wp[idx] = v;
}

__global__ void repack_all(const float* ew2, const float* ew3, const float* ew4,
                           const float* dw1, const float* dw2, const float* dw3,
                           const float* dw4,
                           float* wt_e2, float* wt_e3, float* wt_e4, float* wt_d1,
                           float* wtT_d2, float* wtT_d3, float* w4p)
{
    int idx = blockIdx.x*256 + threadIdx.x;
    if (idx < 131072) { rp_conv(ew2, wt_e2, 64, 128, 16, idx); return; }
    idx -= 131072;
    if (idx < 294912) { rp_conv(ew3, wt_e3, 128, 256, 9, idx); return; }
    idx -= 294912;
    if (idx < 589824) { rp_conv(ew4, wt_e4, 256, 256, 9, idx); return; }
    idx -= 589824;
    if (idx < 294912) { rp_conv(dw1, wt_d1, 256, 128, 9, idx); return; }
    idx -= 294912;
    if (idx < 131072) { rp_convT(dw2, wtT_d2, 128, 64, idx); return; }
    idx -= 131072;
    if (idx < 65536)  { rp_convT(dw3, wtT_d3, 64, 64, idx); return; }
    idx -= 65536;
    if (idx < 9216)   { rp_w4(dw4, w4p, idx); }
}

// ---------------------------------------------------------------------------
// Direct conv (FFMA) — enc1 only (Cin=3).
// ---------------------------------------------------------------------------
template<int K, int S, int CIN_T>
__global__ __launch_bounds__(128)
void conv2d_tiled(const float* __restrict__ in, const float* __restrict__ w,
                  const float* __restrict__ bias, float* __restrict__ out,
                  int Cin, int H, int W, int Cout, int Ho, int Wo,
                  int pad, int relu)
{
    constexpr int IH = 3*S + K;
    constexpr int IW = 15*S + K;
    constexpr int KK = K*K;
    __shared__ __align__(16) float s_in[CIN_T*IH*IW];
    __shared__ __align__(16) float s_w [CIN_T*KK*64];

    const int tid = threadIdx.x;
    const int px  = tid & 15;
    const int cg  = tid >> 4;
    const int hb  = Ho >> 2;
    const int b   = blockIdx.y / hb;
    const int oy0 = (blockIdx.y % hb) * 4;
    const int ox0 = blockIdx.x * 16;
    const int co0 = blockIdx.z * 64;
    const int iy0 = oy0*S - pad;
    const int ix0 = ox0*S - pad;

    float acc[4][8];
#pragma unroll
    for (int p = 0; p < 4; p++)
#pragma unroll
        for (int c = 0; c < 8; c++) acc[p][c] = 0.f;

    for (int ci0 = 0; ci0 < Cin; ci0 += CIN_T) {
        for (int idx = tid; idx < CIN_T*IH*IW; idx += 128) {
            int ci  = idx / (IH*IW);
            int rem = idx % (IH*IW);
            int r   = rem / IW, c = rem % IW;
            int iy  = iy0 + r, ix = ix0 + c;
            float v = 0.f;
            if ((unsigned)iy < (unsigned)H && (unsigned)ix < (unsigned)W &&
                (ci0 + ci) < Cin)
                v = in[((b*Cin + ci0 + ci)*H + iy)*W + ix];
            s_in[idx] = v;
        }
        for (int idx = tid; idx < CIN_T*KK*64; idx += 128) {
            int co  = idx & 63;
            int rem = idx >> 6;
            int kk  = rem % KK;
            int ci  = rem / KK;
            float v = 0.f;
            if ((ci0 + ci) < Cin)
                v = w[((co0 + co)*Cin + ci0 + ci)*KK + kk];
            s_w[idx] = v;
        }
        __syncthreads();

        for (int ci = 0; ci < CIN_T; ci++) {
#pragma unroll
            for (int kh = 0; kh < K; kh++) {
#pragma unroll
                for (int kw = 0; kw < K; kw++) {
                    const float4* wp =
                        (const float4*)(s_w + ((ci*KK + kh*K + kw) << 6) + (cg << 3));
                    float4 w0 = wp[0], w1 = wp[1];
#pragma unroll
                    for (int p = 0; p < 4; p++) {
                        float iv = s_in[(ci*IH + p*S + kh)*IW + px*S + kw];
                        acc[p][0] += iv*w0.x; acc[p][1] += iv*w0.y;
                        acc[p][2] += iv*w0.z; acc[p][3] += iv*w0.w;
                        acc[p][4] += iv*w1.x; acc[p][5] += iv*w1.y;
                        acc[p][6] += iv*w1.z; acc[p][7] += iv*w1.w;
                    }
                }
            }
        }
        __syncthreads();
    }

#pragma unroll
    for (int c = 0; c < 8; c++) {
        int co = co0 + (cg << 3) + c;
        float bv = bias[co];
#pragma unroll
        for (int p = 0; p < 4; p++) {
            float v = acc[p][c] + bv;
            if (relu) v = fmaxf(v, 0.f);
            out[((b*Cout + co)*Ho + oy0 + p)*Wo + ox0 + px] = v;
        }
    }
}

// ---------------------------------------------------------------------------
// Helpers
// ---------------------------------------------------------------------------
__global__ void cnorm_kernel(const float* __restrict__ cb, float* __restrict__ cn) {
    int row  = (blockIdx.x*blockDim.x + threadIdx.x) >> 5;
    int lane = threadIdx.x & 31;
    if (row >= 4096) return;
    const float* p = cb + (size_t)row*256;
    float s = 0.f;
    for (int c = lane; c < 256; c += 32) { float v = p[c]; s += v*v; }
#pragma unroll
    for (int o = 16; o; o >>= 1) s += __shfl_down_sync(0xffffffffu, s, o);
    if (!lane) cn[row] = s;
}

__global__ void zero_loss(double* l) { if (threadIdx.x < 4) l[threadIdx.x] = 0.0; }

__global__ void write_loss(const double* __restrict__ l, float* __restrict__ o) {
    if (threadIdx.x < 4)
        o[threadIdx.x] = (float)(l[threadIdx.x] * (1.0/(65536.0*256.0)));
}

__global__ void z_to_tokens(const float* __restrict__ z,
                            float* __restrict__ resid, float* __restrict__ qsum)
{
    __shared__ float t[32][33];
    int b  = blockIdx.z;
    int s0 = blockIdx.x*32;
    int c0 = blockIdx.y*32;
    int x  = threadIdx.x;
    for (int y = threadIdx.y; y < 32; y += 8)
        t[y][x] = z[((size_t)b*256 + c0 + y)*4096 + s0 + x];
    __syncthreads();
    for (int y = threadIdx.y; y < 32; y += 8) {
        size_t o = ((size_t)b*4096 + s0 + y)*256 + c0 + x;
        resid[o] = t[x][y];
        qsum[o]  = 0.f;
    }
}

__global__ void tokens_to_z(const float* __restrict__ qsum,
                            float* __restrict__ z1, float* __restrict__ z2)
{
    __shared__ float t[32][33];
    int b  = blockIdx.z;
    int c0 = blockIdx.x*32;
    int s0 = blockIdx.y*32;
    int x  = threadIdx.x;
    for (int y = threadIdx.y; y < 32; y += 8)
        t[y][x] = qsum[((size_t)b*4096 + s0 + y)*256 + c0 + x];
    __syncthreads();
    for (int y = threadIdx.y; y < 32; y += 8) {
        float v = t[x][y];
        size_t o = ((size_t)b*256 + c0 + y)*4096 + s0 + x;
        z1[o] = v; z2[o] = v;
    }
}

// ---------------------------------------------------------------------------
// Launch
// ---------------------------------------------------------------------------
extern "C" void kernel_launch(void* const* d_in, const int* in_sizes, int n_in,
                              void* d_out, int out_size)
{
    const float* x   = (const float*)d_in[0];
    const float* ew1 = (const float*)d_in[1];  const float* eb1 = (const float*)d_in[2];
    const float* ew2 = (const float*)d_in[3];  const float* eb2 = (const float*)d_in[4];
    const float* ew3 = (const float*)d_in[5];  const float* eb3 = (const float*)d_in[6];
    const float* ew4 = (const float*)d_in[7];  const float* eb4 = (const float*)d_in[8];
    const float* cbs = (const float*)d_in[9];
    const float* dw1 = (const float*)d_in[10]; const float* db1 = (const float*)d_in[11];
    const float* dw2 = (const float*)d_in[12]; const float* db2 = (const float*)d_in[13];
    const float* dw3 = (const float*)d_in[14]; const float* db3 = (const float*)d_in[15];
    const float* dw4 = (const float*)d_in[16]; const float* db4 = (const float*)d_in[17];
    float* out = (float*)d_out;

    float *h1, *h2, *h3, *z, *resid, *qsum, *cnorm, *w4p, *wt, *wtT, *d3;
    double* loss; unsigned* rowmin;
    cudaGetSymbolAddress((void**)&h1,    g_h1);
    cudaGetSymbolAddress((void**)&h2,    g_h2);
    cudaGetSymbolAddress((void**)&h3,    g_h3);
    cudaGetSymbolAddress((void**)&z,     g_z);
    cudaGetSymbolAddress((void**)&resid, g_resid);
    cudaGetSymbolAddress((void**)&qsum,  g_qsum);
    cudaGetSymbolAddress((void**)&loss,  g_loss);
    cudaGetSymbolAddress((void**)&cnorm, g_cnorm);
    cudaGetSymbolAddress((void**)&rowmin,g_rowmin);
    cudaGetSymbolAddress((void**)&w4p,   g_w4p);
    cudaGetSymbolAddress((void**)&wt,    g_wt);
    cudaGetSymbolAddress((void**)&wtT,   g_wtT);
    cudaGetSymbolAddress((void**)&d3,    g_d3);

    float* wt_e2  = wt;                               // 16*64*128  = 131072
    float* wt_e3  = wt + 131072;                      // 9*128*256  = 294912
    float* wt_e4  = wt + 131072 + 294912;             // 9*256*256  = 589824
    float* wt_d1  = wt + 131072 + 294912 + 589824;    // 9*256*128  = 294912
    float* wtT_d2 = wtT;                              // 16*128*64  = 131072
    float* wtT_d3 = wtT + 131072;                     // 16*64*64   = 65536

    // output layout: recon | indices | commit_loss | quantized
    float* recO   = out;
    float* idxO   = out + 12582912;
    float* lossO  = idxO + 262144;
    float* quantO = lossO + 4;

    const int PA_SMEM  = 2*PLW*4 + 512;               // 34304
    const int CT4_SMEM = (16*792 + 9*16*16)*4;        // 59904
    cudaFuncSetAttribute(vq_gemm_approx, cudaFuncAttributeMaxDynamicSharedMemorySize, PA_SMEM);
    cudaFuncSetAttribute(convT4_ffma,    cudaFuncAttributeMaxDynamicSharedMemorySize, CT4_SMEM);

    // prep
    repack_all     <<<5924, 256>>>(ew2, ew3, ew4, dw1, dw2, dw3, dw4,
                                   wt_e2, wt_e3, wt_e4, wt_d1, wtT_d2, wtT_d3, w4p);
    cnorm_kernel   <<<512, 256>>>(cbs, cnorm);
    zero_loss      <<<1, 32>>>(loss);
    init_rowmin_all<<<256, 1024>>>(rowmin);

    // ---- encoder (exact fp32) ----
    conv2d_tiled<4,2,4><<<dim3(8, 32*16, 1), 128>>>(x, ew1, eb1, h1, 3, 256, 256, 64, 128, 128, 1, 1);
    conv_ffma<4,2><<<dim3(512, 1), 256>>>(h1, wt_e2, eb2, h2,  64, 128, 128, 128, 1);
    conv_ffma<3,1><<<dim3(512, 2), 256>>>(h2, wt_e3, eb3, h3, 128,  64,  64, 256, 1);
    conv_ffma<3,1><<<dim3(512, 2), 256>>>(h3, wt_e4, eb4, z,  256,  64,  64, 256, 0);

    // ---- residual VQ: single-MMA tf32 approx distances (bf16 D) + exact rescore ----
    z_to_tokens<<<dim3(128, 8, 16), dim3(32, 8)>>>(z, resid, qsum);
    __nv_bfloat16* Dh = (__nv_bfloat16*)d3;
    for (int s = 0; s < 4; s++) {
        vq_gemm_approx  <<<dim3(512, 8), 256, PA_SMEM>>>(resid, cbs + (size_t)s*1024*256,
                                                         cnorm + s*1024, Dh, rowmin + s*65536);
        vq_select_update<<<8192, 256>>>(Dh, cbs + (size_t)s*1024*256, cnorm + s*1024,
                                        rowmin + s*65536, resid, qsum, idxO, s, loss);
    }
    write_loss <<<1, 32>>>(loss, lossO);
    tokens_to_z<<<dim3(8, 128, 16), dim3(32, 8)>>>(qsum, z, quantO);

    // ---- decoder (FFMA, exact) ----
    conv_ffma<3,1><<<dim3(512, 1), 256>>>(z, wt_d1, db1, h2, 256, 64, 64, 128, 1);
    convT_ffma<<<dim3( 256, 1, 4), 256>>>(h2, wtT_d2, db2, h1, 128,  64,  64, 6, 12);
    convT_ffma<<<dim3(1024, 1, 4), 256>>>(h1, wtT_d3, db3, d3,  64, 128, 128, 7, 14);
    convT4_ffma<<<4096, 256, CT4_SMEM>>>(d3, w4p, db4, recO);
}

// round 13
// speedup vs baseline: 1.1852x; 1.0278x over previous
#include <cuda_runtime.h>
#include <cuda_bf16.h>
#include <cstdint>

// ---------------------------------------------------------------------------
// Scratch (device globals — no allocation allowed)
// ---------------------------------------------------------------------------
__device__ float g_h1[16*64*128*128];          // enc1 out / dec2 out (reused)
__device__ float g_h2[16*128*64*64];           // enc2 out / dec1 out (reused)
__device__ float g_h3[16*256*64*64];           // enc3 out
__device__ float g_z [16*256*64*64];           // enc4 out (z) / quantized NCHW (reused)
__device__ float g_resid[65536*256];
__device__ float g_qsum [65536*256];
__device__ double g_loss[4];
__device__ float g_cnorm[4*1024];
__device__ unsigned g_rowmin[4*65536];
__device__ float g_w4p[64*16*4];               // dec_w4 repacked [ci][pt(16)][co pad 4]
__device__ float g_wt[1310720];                // conv weights repacked [tap][ci][co]
__device__ float g_wtT[196608];                // convT weights [parity][tap][ci][co]
__device__ float g_d3[16*64*256*256];          // dec3 out; ALSO the 65536x1024 D (bf16)

// ---------------------------------------------------------------------------
// tf32 helpers (approximate Phase-A path only; correctness never depends on it)
// ---------------------------------------------------------------------------
__device__ __forceinline__ uint32_t f2tf(float f) {
    uint32_t u;
    asm("cvt.rna.tf32.f32 %0, %1;" : "=r"(u) : "f"(f));
    return u;
}

__device__ __forceinline__ void mma_tf32(float* c, const uint32_t* a,
                                         uint32_t b0, uint32_t b1) {
    asm volatile(
        "mma.sync.aligned.m16n8k8.row.col.f32.tf32.tf32.f32 "
        "{%0,%1,%2,%3},{%4,%5,%6,%7},{%8,%9},{%0,%1,%2,%3};"
        : "+f"(c[0]), "+f"(c[1]), "+f"(c[2]), "+f"(c[3])
        : "r"(a[0]), "r"(a[1]), "r"(a[2]), "r"(a[3]), "r"(b0), "r"(b1));
}

// order-preserving float <-> uint32 (for atomicMin)
__device__ __forceinline__ unsigned fenc(float d) {
    unsigned u = __float_as_uint(d);
    return (u & 0x80000000u) ? ~u : (u | 0x80000000u);
}
__device__ __forceinline__ float fdec(unsigned e) {
    unsigned u = (e & 0x80000000u) ? (e & 0x7FFFFFFFu) : ~e;
    return __uint_as_float(u);
}

static const int PLW = 128*33;   // one smem plane in words (stride 33: conflict-free)

// ---------------------------------------------------------------------------
// Phase A: approximate distance matrix, single tf32 MMA, D stored as bf16.
// D[m,n] = cn[n] - 2 * R[m,:].cb[n,:]; per-row min -> rowmin (atomicMin).
// ---------------------------------------------------------------------------
__global__ __launch_bounds__(256)
void vq_gemm_approx(const float* __restrict__ R, const float* __restrict__ cb,
                    const float* __restrict__ cn, __nv_bfloat16* __restrict__ D,
                    unsigned* __restrict__ rowmin)
{
    extern __shared__ uint32_t dyn[];
    uint32_t* sA = dyn;
    uint32_t* sB = dyn + PLW;
    unsigned* sMin = (unsigned*)(dyn + 2*PLW);

    const int tid  = threadIdx.x;
    const int lane = tid & 31;
    const int warp = tid >> 5;
    const int wm = warp & 1;
    const int wn = warp >> 1;
    const int m0 = blockIdx.x << 7;
    const int n0 = blockIdx.y << 7;

    float acc[4][4][4];
#pragma unroll
    for (int i = 0; i < 4; i++)
#pragma unroll
        for (int j = 0; j < 4; j++)
#pragma unroll
            for (int k = 0; k < 4; k++) acc[i][j][k] = 0.f;

    if (tid < 128) sMin[tid] = 0xFFFFFFFFu;

    for (int k0 = 0; k0 < 256; k0 += 32) {
#pragma unroll
        for (int i = 0; i < 4; i++) {
            int idx4 = tid + i*256;
            int m  = idx4 >> 3;
            int kq = idx4 & 7;
            int oa = m*33 + kq*4;
            float4 a = *(const float4*)(R  + (size_t)(m0 + m)*256 + k0 + kq*4);
            sA[oa+0] = f2tf(a.x); sA[oa+1] = f2tf(a.y);
            sA[oa+2] = f2tf(a.z); sA[oa+3] = f2tf(a.w);
            float4 b = *(const float4*)(cb + (size_t)(n0 + m)*256 + k0 + kq*4);
            sB[oa+0] = f2tf(b.x); sB[oa+1] = f2tf(b.y);
            sB[oa+2] = f2tf(b.z); sB[oa+3] = f2tf(b.w);
        }
        __syncthreads();

#pragma unroll
        for (int ks = 0; ks < 4; ks++) {
            const int kb = ks*8 + (lane & 3);
            uint32_t bf[4][2];
#pragma unroll
            for (int fn = 0; fn < 4; fn++) {
                int n = wn*32 + fn*8 + (lane >> 2);
                bf[fn][0] = sB[n*33 + kb];  bf[fn][1] = sB[n*33 + kb + 4];
            }
#pragma unroll
            for (int fm = 0; fm < 4; fm++) {
                int r = wm*64 + fm*16 + (lane >> 2);
                uint32_t af[4];
                af[0] = sA[r*33 + kb];     af[1] = sA[(r+8)*33 + kb];
                af[2] = sA[r*33 + kb+4];   af[3] = sA[(r+8)*33 + kb+4];
#pragma unroll
                for (int fn = 0; fn < 4; fn++)
                    mma_tf32(acc[fm][fn], af, bf[fn][0], bf[fn][1]);
            }
        }
        __syncthreads();
    }

    float cnv[4][2];
#pragma unroll
    for (int fn = 0; fn < 4; fn++) {
        int col = n0 + wn*32 + fn*8 + 2*(lane & 3);
        cnv[fn][0] = cn[col];
        cnv[fn][1] = cn[col + 1];
    }
#pragma unroll
    for (int fm = 0; fm < 4; fm++) {
#pragma unroll
        for (int h = 0; h < 2; h++) {
            int rl = wm*64 + fm*16 + (lane >> 2) + h*8;
            int rg = m0 + rl;
            float mn = 3.402823466e38f;
#pragma unroll
            for (int fn = 0; fn < 4; fn++) {
                int col = n0 + wn*32 + fn*8 + 2*(lane & 3);
                float vx = cnv[fn][0] - 2.f*acc[fm][fn][h*2 + 0];
                float vy = cnv[fn][1] - 2.f*acc[fm][fn][h*2 + 1];
                mn = fminf(mn, fminf(vx, vy));
                *(__nv_bfloat162*)(D + (size_t)rg*1024 + col) =
                    __floats2bfloat162_rn(vx, vy);
            }
            atomicMin(&sMin[rl], fenc(mn));
        }
    }
    __syncthreads();
    if (tid < 128) atomicMin(&rowmin[m0 + tid], sMin[tid]);
}

__global__ void init_rowmin_all(unsigned* rowmin) {
    rowmin[blockIdx.x*1024 + threadIdx.x] = 0xFFFFFFFFu;
}

// ---------------------------------------------------------------------------
// Phase B: one warp per token; bf16x2 vectorized scan, exact-FFMA rescore of
// candidates within EPS of the approx row-min, lowest-index tie-break,
// fused vq_update.
// ---------------------------------------------------------------------------
__global__ __launch_bounds__(256)
void vq_select_update(const __nv_bfloat16* __restrict__ D, const float* __restrict__ cb,
                      const float* __restrict__ cn,
                      const unsigned* __restrict__ rowmin,
                      float* __restrict__ resid, float* __restrict__ qsum,
                      float* __restrict__ idx_out, int stage,
                      double* __restrict__ lossAcc)
{
    __shared__ double sLoss[8];
    const int warp = threadIdx.x >> 5;
    const int lane = threadIdx.x & 31;
    const int t = blockIdx.x*8 + warp;

    const __nv_bfloat16* drow = D + (size_t)t*1024;
    const float thr = fdec(rowmin[t]) + 0.03f;

    float4 r0 = *(const float4*)(resid + (size_t)t*256 + lane*8);
    float4 r1 = *(const float4*)(resid + (size_t)t*256 + lane*8 + 4);

    float bestd = 3.402823466e38f;
    int   bestn = 0x7FFFFFFF;

    auto rescore = [&](int j) {
        const float* c = cb + (size_t)j*256;
        float4 c0 = *(const float4*)(c + lane*8);
        float4 c1 = *(const float4*)(c + lane*8 + 4);
        float dot = r0.x*c0.x + r0.y*c0.y + r0.z*c0.z + r0.w*c0.w
                  + r1.x*c1.x + r1.y*c1.y + r1.z*c1.z + r1.w*c1.w;
#pragma unroll
        for (int o = 16; o; o >>= 1)
            dot += __shfl_xor_sync(0xffffffffu, dot, o);
        float de = cn[j] - 2.f*dot;
        if (de < bestd || (de == bestd && j < bestn)) { bestd = de; bestn = j; }
    };

    for (int j0 = 0; j0 < 1024; j0 += 64) {
        __nv_bfloat162 dv2 = *(const __nv_bfloat162*)(drow + j0 + lane*2);
        float2 dd = __bfloat1622float2(dv2);
        unsigned me = __ballot_sync(0xffffffffu, dd.x <= thr);
        unsigned mo = __ballot_sync(0xffffffffu, dd.y <= thr);
        while (me) { int s = __ffs(me) - 1; me &= me - 1; rescore(j0 + 2*s); }
        while (mo) { int s = __ffs(mo) - 1; mo &= mo - 1; rescore(j0 + 2*s + 1); }
    }

    const float* q = cb + (size_t)bestn*256;
    float4 q0 = *(const float4*)(q + lane*8);
    float4 q1 = *(const float4*)(q + lane*8 + 4);
    float4 s0 = *(float4*)(qsum + (size_t)t*256 + lane*8);
    float4 s1 = *(float4*)(qsum + (size_t)t*256 + lane*8 + 4);

    float ls = 0.f;
    {
        float d;
        d = q0.x-r0.x; ls += d*d;  d = q0.y-r0.y; ls += d*d;
        d = q0.z-r0.z; ls += d*d;  d = q0.w-r0.w; ls += d*d;
        d = q1.x-r1.x; ls += d*d;  d = q1.y-r1.y; ls += d*d;
        d = q1.z-r1.z; ls += d*d;  d = q1.w-r1.w; ls += d*d;
    }
    s0.x += q0.x; s0.y += q0.y; s0.z += q0.z; s0.w += q0.w;
    s1.x += q1.x; s1.y += q1.y; s1.z += q1.z; s1.w += q1.w;
    r0.x -= q0.x; r0.y -= q0.y; r0.z -= q0.z; r0.w -= q0.w;
    r1.x -= q1.x; r1.y -= q1.y; r1.z -= q1.z; r1.w -= q1.w;
    *(float4*)(qsum  + (size_t)t*256 + lane*8)     = s0;
    *(float4*)(qsum  + (size_t)t*256 + lane*8 + 4) = s1;
    *(float4*)(resid + (size_t)t*256 + lane*8)     = r0;
    *(float4*)(resid + (size_t)t*256 + lane*8 + 4) = r1;

#pragma unroll
    for (int o = 16; o; o >>= 1) ls += __shfl_down_sync(0xffffffffu, ls, o);
    if (lane == 0) {
        sLoss[warp] = (double)ls;
        idx_out[(t >> 12)*16384 + stage*4096 + (t & 4095)] = (float)bestn;
    }
    __syncthreads();
    if (threadIdx.x == 0) {
        double tot = 0.0;
#pragma unroll
        for (int w = 0; w < 8; w++) tot += sLoss[w];
        atomicAdd(lossAcc + stage, tot);
    }
}

// ---------------------------------------------------------------------------
// Implicit-GEMM FFMA conv (3x3 s1 or 4x4 s2, pad 1). Output 64x64 per image.
// Double-buffered smem, register-staged prefetch, single sync per chunk.
// ---------------------------------------------------------------------------
template<int KSZ, int S>
__global__ __launch_bounds__(256, 2)
void conv_ffma(const float* __restrict__ in, const float* __restrict__ wt,
               const float* __restrict__ bias, float* __restrict__ out,
               int Cin, int Hin, int Win, int Cout, int relu)
{
    __shared__ float sA[2][16*128];
    __shared__ float sB[2][16*128];
    const int tid = threadIdx.x;
    const int tx = tid & 15;
    const int ty = tid >> 4;
    const int m0  = blockIdx.x << 7;
    const int co0 = blockIdx.y << 7;
    const int b   = m0 >> 12;
    const int y0  = (m0 & 4095) >> 6;
    const int cpt = Cin >> 4;
    const int NCH = KSZ*KSZ*cpt;

    float acc[8][8];
#pragma unroll
    for (int i = 0; i < 8; i++)
#pragma unroll
        for (int j = 0; j < 8; j++) acc[i][j] = 0.f;

    float ra[8], rb[8];

    auto loadc = [&](int q) {
        int tap = q / cpt;
        int ci0 = (q - tap*cpt) << 4;
        int dy = tap/KSZ - 1, dx = tap%KSZ - 1;
#pragma unroll
        for (int v = 0; v < 8; v++) {
            int idx = tid + v*256;
            int ci = idx >> 7, pix = idx & 127;
            int iy = (y0 + (pix >> 6))*S + dy;
            int ix = (pix & 63)*S + dx;
            float val = 0.f;
            if ((unsigned)iy < (unsigned)Hin && (unsigned)ix < (unsigned)Win)
                val = in[((size_t)(b*Cin + ci0 + ci)*Hin + iy)*Win + ix];
            ra[v] = val;
            rb[v] = wt[((size_t)tap*Cin + ci0 + ci)*Cout + co0 + pix];
        }
    };
    auto storec = [&](int buf) {
#pragma unroll
        for (int v = 0; v < 8; v++) {
            int idx = tid + v*256;
            int ci = idx >> 7, pix = idx & 127;
            sA[buf][ci*128 + pix] = ra[v];
            sB[buf][ci*128 + pix] = rb[v];
        }
    };

    loadc(0); storec(0); __syncthreads();
    for (int q = 0; q < NCH; q++) {
        if (q + 1 < NCH) loadc(q + 1);
        const float* pA = sA[q & 1];
        const float* pB = sB[q & 1];
#pragma unroll
        for (int kk = 0; kk < 16; kk++) {
            float4 a0 = *(const float4*)&pA[kk*128 + tx*8];
            float4 a1 = *(const float4*)&pA[kk*128 + tx*8 + 4];
            float4 b0 = *(const float4*)&pB[kk*128 + ty*8];
            float4 b1 = *(const float4*)&pB[kk*128 + ty*8 + 4];
            float av[8] = {a0.x,a0.y,a0.z,a0.w,a1.x,a1.y,a1.z,a1.w};
            float bv[8] = {b0.x,b0.y,b0.z,b0.w,b1.x,b1.y,b1.z,b1.w};
#pragma unroll
            for (int i = 0; i < 8; i++)
#pragma unroll
                for (int j = 0; j < 8; j++) acc[i][j] += av[i]*bv[j];
        }
        if (q + 1 < NCH) storec((q + 1) & 1);
        __syncthreads();
    }

    const int yr = y0 + (tx >> 3);
    const int xc = (tx*8) & 63;
#pragma unroll
    for (int j = 0; j < 8; j++) {
        int co = co0 + ty*8 + j;
        float bv = bias[co];
        float4 v0, v1;
        v0.x = acc[0][j]+bv; v0.y = acc[1][j]+bv; v0.z = acc[2][j]+bv; v0.w = acc[3][j]+bv;
        v1.x = acc[4][j]+bv; v1.y = acc[5][j]+bv; v1.z = acc[6][j]+bv; v1.w = acc[7][j]+bv;
        if (relu) {
            v0.x = fmaxf(v0.x,0.f); v0.y = fmaxf(v0.y,0.f); v0.z = fmaxf(v0.z,0.f); v0.w = fmaxf(v0.w,0.f);
            v1.x = fmaxf(v1.x,0.f); v1.y = fmaxf(v1.y,0.f); v1.z = fmaxf(v1.z,0.f); v1.w = fmaxf(v1.w,0.f);
        }
        float* p = out + ((size_t)(b*Cout + co)*4096 + yr*64 + xc);
        *(float4*)p = v0;
        *(float4*)(p + 4) = v1;
    }
}

// ---------------------------------------------------------------------------
// Implicit-GEMM FFMA convT (k4 s2 p1), parity-decomposed, Cout=64, relu.
// Coalesced parity stores (mx = tx + 32*i).
// ---------------------------------------------------------------------------
__global__ __launch_bounds__(256, 2)
void convT_ffma(const float* __restrict__ in, const float* __restrict__ wtT,
                const float* __restrict__ bias, float* __restrict__ out,
                int Cin, int Hin, int Win, int wsh, int hwsh)
{
    __shared__ float sA[2][16*256];
    __shared__ float sB[2][16*64];
    const int tid = threadIdx.x;
    const int tx = tid & 31;
    const int ty = tid >> 5;
    const int P0 = blockIdx.x << 8;
    const int b   = P0 >> hwsh;
    const int lp  = P0 & ((1 << hwsh) - 1);
    const int my0 = lp >> wsh;
    const int p  = blockIdx.z;
    const int ey = p >> 1, ex = p & 1;
    const float* wtp = wtT + (size_t)p*4*Cin*64;
    const int Wo  = Win*2;
    const int HWo = (Hin*Win)*4;
    const int cpt = Cin >> 4;
    const int NCH = 4*cpt;

    float acc[8][8];
#pragma unroll
    for (int i = 0; i < 8; i++)
#pragma unroll
        for (int j = 0; j < 8; j++) acc[i][j] = 0.f;

    float ra[16], rb[4];

    auto loadc = [&](int q) {
        int t = q / cpt;
        int ci0 = (q - t*cpt) << 4;
        int jy = t >> 1, jx = t & 1;
        int ry = (ey == 0) ? (jy == 0 ? 0 : -1) : (jy == 0 ? 1 : 0);
        int rx = (ex == 0) ? (jx == 0 ? 0 : -1) : (jx == 0 ? 1 : 0);
#pragma unroll
        for (int v = 0; v < 16; v++) {
            int idx = tid + v*256;
            int ci = idx >> 8, pix = idx & 255;
            int iy = my0 + (pix >> wsh) + ry;
            int ix = (pix & (Win-1)) + rx;
            float val = 0.f;
            if ((unsigned)iy < (unsigned)Hin && (unsigned)ix < (unsigned)Win)
                val = in[((size_t)(b*Cin + ci0 + ci)*Hin + iy)*Win + ix];
            ra[v] = val;
        }
#pragma unroll
        for (int v = 0; v < 4; v++) {
            int idx = tid + v*256;
            int ci = idx >> 6, n = idx & 63;
            rb[v] = wtp[((size_t)t*Cin + ci0 + ci)*64 + n];
        }
    };
    auto storec = [&](int buf) {
#pragma unroll
        for (int v = 0; v < 16; v++) {
            int idx = tid + v*256;
            int ci = idx >> 8, pix = idx & 255;
            sA[buf][ci*256 + pix] = ra[v];
        }
#pragma unroll
        for (int v = 0; v < 4; v++) {
            int idx = tid + v*256;
            int ci = idx >> 6, n = idx & 63;
            sB[buf][ci*64 + n] = rb[v];
        }
    };

    loadc(0); storec(0); __syncthreads();
    for (int q = 0; q < NCH; q++) {
        if (q + 1 < NCH) loadc(q + 1);
        const float* pA = sA[q & 1];
        const float* pB = sB[q & 1];
#pragma unroll
        for (int kk = 0; kk < 16; kk++) {
            float av[8];
#pragma unroll
            for (int i = 0; i < 8; i++)
                av[i] = pA[kk*256 + tx + 32*i];
            float4 b0 = *(const float4*)&pB[kk*64 + ty*8];
            float4 b1 = *(const float4*)&pB[kk*64 + ty*8 + 4];
            float bv[8] = {b0.x,b0.y,b0.z,b0.w,b1.x,b1.y,b1.z,b1.w};
#pragma unroll
            for (int i = 0; i < 8; i++)
#pragma unroll
                for (int j = 0; j < 8; j++) acc[i][j] += av[i]*bv[j];
        }
        if (q + 1 < NCH) storec((q + 1) & 1);
        __syncthreads();
    }

#pragma unroll
    for (int j = 0; j < 8; j++) {
        int co = ty*8 + j;
        float bv = bias[co];
        float* pb = out + (size_t)(b*64 + co)*HWo + ex;
#pragma unroll
        for (int i = 0; i < 8; i++) {
            int gp = lp + tx + 32*i;
            int my = gp >> wsh;
            int mx = gp & (Win-1);
            int oy = 2*my + ey;
            pb[oy*Wo + 2*mx] = fmaxf(acc[i][j] + bv, 0.f);
        }
    }
}

// ---------------------------------------------------------------------------
// convT4 (k4 s2 p1, Cin=64 -> Cout=3, tanh): per-parity 4-tap form (48 FFMA/ci
// vs 108 with the 9-tau zero-padded packing). Weights wp[ci][pt(16)][co pad 4].
// Dynamic smem: 16*792 + 1024 floats = 54784 B.
// ---------------------------------------------------------------------------
__global__ __launch_bounds__(256)
void convT4_ffma(const float* __restrict__ in, const float* __restrict__ wp,
                 const float* __restrict__ bias, float* __restrict__ out)
{
    extern __shared__ float dynf[];
    float* sA = dynf;              // [16 ci][3 rows][264]
    float* sB = dynf + 16*792;     // [16 ci][16 pt][4]

    const int tid = threadIdx.x;
    const int b  = blockIdx.x >> 8;
    const int my = blockIdx.x & 255;
    const float* inb = in + (size_t)b*64*65536;

    float acc[12];
#pragma unroll
    for (int i = 0; i < 12; i++) acc[i] = 0.f;

    for (int ci0 = 0; ci0 < 64; ci0 += 16) {
        for (int idx = tid; idx < 16*3*258; idx += 256) {
            int ci = idx / 774;
            int rem = idx - ci*774;
            int r = rem / 258, c = rem - r*258;
            int iy = my - 1 + r, ix = c - 1;
            float v = 0.f;
            if ((unsigned)iy < 256u && (unsigned)ix < 256u)
                v = inb[((size_t)(ci0 + ci)*256 + iy)*256 + ix];
            sA[ci*792 + r*264 + c] = v;
        }
        for (int idx = tid; idx < 1024; idx += 256)
            sB[idx] = wp[ci0*64 + idx];
        __syncthreads();

        for (int ci = 0; ci < 16; ci++) {
            float n[9];
#pragma unroll
            for (int r = 0; r < 3; r++)
#pragma unroll
                for (int c = 0; c < 3; c++)
                    n[r*3 + c] = sA[ci*792 + r*264 + c + tid];
#pragma unroll
            for (int pt = 0; pt < 16; pt++) {
                const int p = pt >> 2, t = pt & 3;
                const int ey = p >> 1, ex = p & 1;
                const int jy = t >> 1, jx = t & 1;
                const int ry = (ey == 0) ? (jy == 0 ? 0 : -1) : (jy == 0 ? 1 : 0);
                const int rx = (ex == 0) ? (jx == 0 ? 0 : -1) : (jx == 0 ? 1 : 0);
                const int ni = (1 + ry)*3 + (1 + rx);
                float a = n[ni];
                const float4 w = *(const float4*)&sB[ci*64 + pt*4];
                acc[p*3 + 0] += a*w.x;
                acc[p*3 + 1] += a*w.y;
                acc[p*3 + 2] += a*w.z;
            }
        }
        __syncthreads();
    }

    const int mx = tid;
#pragma unroll
    for (int p = 0; p < 4; p++) {
        int ey = p >> 1, ex = p & 1;
        int oy = 2*my + ey;
#pragma unroll
        for (int co = 0; co < 3; co++) {
            float v = tanhf(acc[p*3 + co] + bias[co]);
            out[(((size_t)b*3 + co)*512 + oy)*512 + 2*mx + ex] = v;
        }
    }
}

// ---------------------------------------------------------------------------
// Fused weight repack (single launch)
// ---------------------------------------------------------------------------
__device__ __forceinline__ void rp_conv(const float* w, float* wt,
                                        int Cin, int Cout, int KK, int idx)
{
    int co = idx % Cout; int r = idx / Cout;
    int ci = r % Cin;    int tap = r / Cin;
    wt[idx] = w[(co*Cin + ci)*KK + tap];
}

__device__ __forceinline__ void rp_convT(const float* w, float* wtT,
                                         int Cin, int Cout, int idx)
{
    int co = idx % Cout; int r = idx / Cout;
    int ci = r % Cin;    int pt = r / Cin;
    int p = pt >> 2, t = pt & 3;
    int ey = p >> 1, ex = p & 1;
    int jy = t >> 1, jx = t & 1;
    int ky = (ey == 0) ? (jy == 0 ? 1 : 3) : (jy == 0 ? 0 : 2);
    int kx = (ex == 0) ? (jx == 0 ? 1 : 3) : (jx == 0 ? 0 : 2);
    wtT[idx] = w[((ci*Cout + co)*4 + ky)*4 + kx];
}

// dec_w4 (ci=64, co=3, 4, 4) -> wp[ci][pt(16)][co pad 4]
__device__ __forceinline__ void rp_w4(const float* w, float* wp, int idx)
{
    int ci = idx >> 6;
    int rem = idx & 63;
    int pt = rem >> 2, c = rem & 3;
    float v = 0.f;
    if (c < 3) {
        int p = pt >> 2, t = pt & 3;
        int ey = p >> 1, ex = p & 1;
        int jy = t >> 1, jx = t & 1;
        int ky = (ey == 0) ? (jy == 0 ? 1 : 3) : (jy == 0 ? 0 : 2);
        int kx = (ex == 0) ? (jx == 0 ? 1 : 3) : (jx == 0 ? 0 : 2);
        v = w[((ci*3 + c)*4 + ky)*4 + kx];
    }
    wp[idx] = v;
}

__global__ void repack_all(const float* ew2, const float* ew3, const float* ew4,
                           const float* dw1, const float* dw2, const float* dw3,
                           const float* dw4,
                           float* wt_e2, float* wt_e3, float* wt_e4, float* wt_d1,
                           float* wtT_d2, float* wtT_d3, float* w4p)
{
    int idx = blockIdx.x*256 + threadIdx.x;
    if (idx < 131072) { rp_conv(ew2, wt_e2, 64, 128, 16, idx); return; }
    idx -= 131072;
    if (idx < 294912) { rp_conv(ew3, wt_e3, 128, 256, 9, idx); return; }
    idx -= 294912;
    if (idx < 589824) { rp_conv(ew4, wt_e4, 256, 256, 9, idx); return; }
    idx -= 589824;
    if (idx < 294912) { rp_conv(dw1, wt_d1, 256, 128, 9, idx); return; }
    idx -= 294912;
    if (idx < 131072) { rp_convT(dw2, wtT_d2, 128, 64, idx); return; }
    idx -= 131072;
    if (idx < 65536)  { rp_convT(dw3, wtT_d3, 64, 64, idx); return; }
    idx -= 65536;
    if (idx < 4096)   { rp_w4(dw4, w4p, idx); }
}

// ---------------------------------------------------------------------------
// Direct conv (FFMA) — enc1 only (Cin=3).
// ---------------------------------------------------------------------------
template<int K, int S, int CIN_T>
__global__ __launch_bounds__(128)
void conv2d_tiled(const float* __restrict__ in, const float* __restrict__ w,
                  const float* __restrict__ bias, float* __restrict__ out,
                  int Cin, int H, int W, int Cout, int Ho, int Wo,
                  int pad, int relu)
{
    constexpr int IH = 3*S + K;
    constexpr int IW = 15*S + K;
    constexpr int KK = K*K;
    __shared__ __align__(16) float s_in[CIN_T*IH*IW];
    __shared__ __align__(16) float s_w [CIN_T*KK*64];

    const int tid = threadIdx.x;
    const int px  = tid & 15;
    const int cg  = tid >> 4;
    const int hb  = Ho >> 2;
    const int b   = blockIdx.y / hb;
    const int oy0 = (blockIdx.y % hb) * 4;
    const int ox0 = blockIdx.x * 16;
    const int co0 = blockIdx.z * 64;
    const int iy0 = oy0*S - pad;
    const int ix0 = ox0*S - pad;

    float acc[4][8];
#pragma unroll
    for (int p = 0; p < 4; p++)
#pragma unroll
        for (int c = 0; c < 8; c++) acc[p][c] = 0.f;

    for (int ci0 = 0; ci0 < Cin; ci0 += CIN_T) {
        for (int idx = tid; idx < CIN_T*IH*IW; idx += 128) {
            int ci  = idx / (IH*IW);
            int rem = idx % (IH*IW);
            int r   = rem / IW, c = rem % IW;
            int iy  = iy0 + r, ix = ix0 + c;
            float v = 0.f;
            if ((unsigned)iy < (unsigned)H && (unsigned)ix < (unsigned)W &&
                (ci0 + ci) < Cin)
                v = in[((b*Cin + ci0 + ci)*H + iy)*W + ix];
            s_in[idx] = v;
        }
        for (int idx = tid; idx < CIN_T*KK*64; idx += 128) {
            int co  = idx & 63;
            int rem = idx >> 6;
            int kk  = rem % KK;
            int ci  = rem / KK;
            float v = 0.f;
            if ((ci0 + ci) < Cin)
                v = w[((co0 + co)*Cin + ci0 + ci)*KK + kk];
            s_w[idx] = v;
        }
        __syncthreads();

        for (int ci = 0; ci < CIN_T; ci++) {
#pragma unroll
            for (int kh = 0; kh < K; kh++) {
#pragma unroll
                for (int kw = 0; kw < K; kw++) {
                    const float4* wp =
                        (const float4*)(s_w + ((ci*KK + kh*K + kw) << 6) + (cg << 3));
                    float4 w0 = wp[0], w1 = wp[1];
#pragma unroll
                    for (int p = 0; p < 4; p++) {
                        float iv = s_in[(ci*IH + p*S + kh)*IW + px*S + kw];
                        acc[p][0] += iv*w0.x; acc[p][1] += iv*w0.y;
                        acc[p][2] += iv*w0.z; acc[p][3] += iv*w0.w;
                        acc[p][4] += iv*w1.x; acc[p][5] += iv*w1.y;
                        acc[p][6] += iv*w1.z; acc[p][7] += iv*w1.w;
                    }
                }
            }
        }
        __syncthreads();
    }

#pragma unroll
    for (int c = 0; c < 8; c++) {
        int co = co0 + (cg << 3) + c;
        float bv = bias[co];
#pragma unroll
        for (int p = 0; p < 4; p++) {
            float v = acc[p][c] + bv;
            if (relu) v = fmaxf(v, 0.f);
            out[((b*Cout + co)*Ho + oy0 + p)*Wo + ox0 + px] = v;
        }
    }
}

// ---------------------------------------------------------------------------
// Helpers
// ---------------------------------------------------------------------------
__global__ void cnorm_kernel(const float* __restrict__ cb, float* __restrict__ cn) {
    int row  = (blockIdx.x*blockDim.x + threadIdx.x) >> 5;
    int lane = threadIdx.x & 31;
    if (row >= 4096) return;
    const float* p = cb + (size_t)row*256;
    float s = 0.f;
    for (int c = lane; c < 256; c += 32) { float v = p[c]; s += v*v; }
#pragma unroll
    for (int o = 16; o; o >>= 1) s += __shfl_down_sync(0xffffffffu, s, o);
    if (!lane) cn[row] = s;
}

__global__ void zero_loss(double* l) { if (threadIdx.x < 4) l[threadIdx.x] = 0.0; }

__global__ void write_loss(const double* __restrict__ l, float* __restrict__ o) {
    if (threadIdx.x < 4)
        o[threadIdx.x] = (float)(l[threadIdx.x] * (1.0/(65536.0*256.0)));
}

__global__ void z_to_tokens(const float* __restrict__ z,
                            float* __restrict__ resid, float* __restrict__ qsum)
{
    __shared__ float t[32][33];
    int b  = blockIdx.z;
    int s0 = blockIdx.x*32;
    int c0 = blockIdx.y*32;
    int x  = threadIdx.x;
    for (int y = threadIdx.y; y < 32; y += 8)
        t[y][x] = z[((size_t)b*256 + c0 + y)*4096 + s0 + x];
    __syncthreads();
    for (int y = threadIdx.y; y < 32; y += 8) {
        size_t o = ((size_t)b*4096 + s0 + y)*256 + c0 + x;
        resid[o] = t[x][y];
        qsum[o]  = 0.f;
    }
}

__global__ void tokens_to_z(const float* __restrict__ qsum,
                            float* __restrict__ z1, float* __restrict__ z2)
{
    __shared__ float t[32][33];
    int b  = blockIdx.z;
    int c0 = blockIdx.x*32;
    int s0 = blockIdx.y*32;
    int x  = threadIdx.x;
    for (int y = threadIdx.y; y < 32; y += 8)
        t[y][x] = qsum[((size_t)b*4096 + s0 + y)*256 + c0 + x];
    __syncthreads();
    for (int y = threadIdx.y; y < 32; y += 8) {
        float v = t[x][y];
        size_t o = ((size_t)b*256 + c0 + y)*4096 + s0 + x;
        z1[o] = v; z2[o] = v;
    }
}

// ---------------------------------------------------------------------------
// Launch
// ---------------------------------------------------------------------------
extern "C" void kernel_launch(void* const* d_in, const int* in_sizes, int n_in,
                              void* d_out, int out_size)
{
    const float* x   = (const float*)d_in[0];
    const float* ew1 = (const float*)d_in[1];  const float* eb1 = (const float*)d_in[2];
    const float* ew2 = (const float*)d_in[3];  const float* eb2 = (const float*)d_in[4];
    const float* ew3 = (const float*)d_in[5];  const float* eb3 = (const float*)d_in[6];
    const float* ew4 = (const float*)d_in[7];  const float* eb4 = (const float*)d_in[8];
    const float* cbs = (const float*)d_in[9];
    const float* dw1 = (const float*)d_in[10]; const float* db1 = (const float*)d_in[11];
    const float* dw2 = (const float*)d_in[12]; const float* db2 = (const float*)d_in[13];
    const float* dw3 = (const float*)d_in[14]; const float* db3 = (const float*)d_in[15];
    const float* dw4 = (const float*)d_in[16]; const float* db4 = (const float*)d_in[17];
    float* out = (float*)d_out;

    float *h1, *h2, *h3, *z, *resid, *qsum, *cnorm, *w4p, *wt, *wtT, *d3;
    double* loss; unsigned* rowmin;
    cudaGetSymbolAddress((void**)&h1,    g_h1);
    cudaGetSymbolAddress((void**)&h2,    g_h2);
    cudaGetSymbolAddress((void**)&h3,    g_h3);
    cudaGetSymbolAddress((void**)&z,     g_z);
    cudaGetSymbolAddress((void**)&resid, g_resid);
    cudaGetSymbolAddress((void**)&qsum,  g_qsum);
    cudaGetSymbolAddress((void**)&loss,  g_loss);
    cudaGetSymbolAddress((void**)&cnorm, g_cnorm);
    cudaGetSymbolAddress((void**)&rowmin,g_rowmin);
    cudaGetSymbolAddress((void**)&w4p,   g_w4p);
    cudaGetSymbolAddress((void**)&wt,    g_wt);
    cudaGetSymbolAddress((void**)&wtT,   g_wtT);
    cudaGetSymbolAddress((void**)&d3,    g_d3);

    float* wt_e2  = wt;                               // 16*64*128  = 131072
    float* wt_e3  = wt + 131072;                      // 9*128*256  = 294912
    float* wt_e4  = wt + 131072 + 294912;             // 9*256*256  = 589824
    float* wt_d1  = wt + 131072 + 294912 + 589824;    // 9*256*128  = 294912
    float* wtT_d2 = wtT;                              // 16*128*64  = 131072
    float* wtT_d3 = wtT + 131072;                     // 16*64*64   = 65536

    // output layout: recon | indices | commit_loss | quantized
    float* recO   = out;
    float* idxO   = out + 12582912;
    float* lossO  = idxO + 262144;
    float* quantO = lossO + 4;

    const int PA_SMEM  = 2*PLW*4 + 512;               // 34304
    const int CT4_SMEM = (16*792 + 1024)*4;           // 54784
    cudaFuncSetAttribute(vq_gemm_approx, cudaFuncAttributeMaxDynamicSharedMemorySize, PA_SMEM);
    cudaFuncSetAttribute(convT4_ffma,    cudaFuncAttributeMaxDynamicSharedMemorySize, CT4_SMEM);

    // prep
    repack_all     <<<5904, 256>>>(ew2, ew3, ew4, dw1, dw2, dw3, dw4,
                                   wt_e2, wt_e3, wt_e4, wt_d1, wtT_d2, wtT_d3, w4p);
    cnorm_kernel   <<<512, 256>>>(cbs, cnorm);
    zero_loss      <<<1, 32>>>(loss);
    init_rowmin_all<<<256, 1024>>>(rowmin);

    // ---- encoder (exact fp32) ----
    conv2d_tiled<4,2,4><<<dim3(8, 32*16, 1), 128>>>(x, ew1, eb1, h1, 3, 256, 256, 64, 128, 128, 1, 1);
    conv_ffma<4,2><<<dim3(512, 1), 256>>>(h1, wt_e2, eb2, h2,  64, 128, 128, 128, 1);
    conv_ffma<3,1><<<dim3(512, 2), 256>>>(h2, wt_e3, eb3, h3, 128,  64,  64, 256, 1);
    conv_ffma<3,1><<<dim3(512, 2), 256>>>(h3, wt_e4, eb4, z,  256,  64,  64, 256, 0);

    // ---- residual VQ: single-MMA tf32 approx distances (bf16 D) + exact rescore ----
    z_to_tokens<<<dim3(128, 8, 16), dim3(32, 8)>>>(z, resid, qsum);
    __nv_bfloat16* Dh = (__nv_bfloat16*)d3;
    for (int s = 0; s < 4; s++) {
        vq_gemm_approx  <<<dim3(512, 8), 256, PA_SMEM>>>(resid, cbs + (size_t)s*1024*256,
                                                         cnorm + s*1024, Dh, rowmin + s*65536);
        vq_select_update<<<8192, 256>>>(Dh, cbs + (size_t)s*1024*256, cnorm + s*1024,
                                        rowmin + s*65536, resid, qsum, idxO, s, loss);
    }
    write_loss <<<1, 32>>>(loss, lossO);
    tokens_to_z<<<dim3(8, 128, 16), dim3(32, 8)>>>(qsum, z, quantO);

    // ---- decoder (FFMA, exact) ----
    conv_ffma<3,1><<<dim3(512, 1), 256>>>(z, wt_d1, db1, h2, 256, 64, 64, 128, 1);
    convT_ffma<<<dim3( 256, 1, 4), 256>>>(h2, wtT_d2, db2, h1, 128,  64,  64, 6, 12);
    convT_ffma<<<dim3(1024, 1, 4), 256>>>(h1, wtT_d3, db3, d3,  64, 128, 128, 7, 14);
    convT4_ffma<<<4096, 256, CT4_SMEM>>>(d3, w4p, db4, recO);
}

// round 14
// speedup vs baseline: 1.2094x; 1.0204x over previous
#include <cuda_runtime.h>
#include <cuda_bf16.h>
#include <cstdint>

// ---------------------------------------------------------------------------
// Scratch (device globals — no allocation allowed)
// ---------------------------------------------------------------------------
__device__ float g_h1[16*64*128*128];          // enc1 out / dec2 out (reused)
__device__ float g_h2[16*128*64*64];           // enc2 out / dec1 out (reused)
__device__ float g_h3[16*256*64*64];           // enc3 out
__device__ float g_z [16*256*64*64];           // enc4 out (z) / quantized NCHW (reused)
__device__ float g_resid[65536*256];
__device__ float g_qsum [65536*256];
__device__ double g_loss[4];
__device__ float g_cnorm[4*1024];
__device__ unsigned g_rowmin[4*65536];
__device__ float g_w4p[64*16*4];               // dec_w4 repacked [ci][pt(16)][co pad 4]
__device__ float g_wt[1313792];                // conv weights repacked [tap][ci][co]
__device__ float g_wtT[196608];                // convT weights [parity][tap][ci][co]
__device__ float g_d3[16*64*256*256];          // dec3 out; ALSO the 65536x1024 D (bf16)

// ---------------------------------------------------------------------------
// tf32 helpers (approximate Phase-A path only; correctness never depends on it)
// ---------------------------------------------------------------------------
__device__ __forceinline__ uint32_t f2tf(float f) {
    uint32_t u;
    asm("cvt.rna.tf32.f32 %0, %1;" : "=r"(u) : "f"(f));
    return u;
}

__device__ __forceinline__ void mma_tf32(float* c, const uint32_t* a,
                                         uint32_t b0, uint32_t b1) {
    asm volatile(
        "mma.sync.aligned.m16n8k8.row.col.f32.tf32.tf32.f32 "
        "{%0,%1,%2,%3},{%4,%5,%6,%7},{%8,%9},{%0,%1,%2,%3};"
        : "+f"(c[0]), "+f"(c[1]), "+f"(c[2]), "+f"(c[3])
        : "r"(a[0]), "r"(a[1]), "r"(a[2]), "r"(a[3]), "r"(b0), "r"(b1));
}

// order-preserving float <-> uint32 (for atomicMin)
__device__ __forceinline__ unsigned fenc(float d) {
    unsigned u = __float_as_uint(d);
    return (u & 0x80000000u) ? ~u : (u | 0x80000000u);
}
__device__ __forceinline__ float fdec(unsigned e) {
    unsigned u = (e & 0x80000000u) ? (e & 0x7FFFFFFFu) : ~e;
    return __uint_as_float(u);
}

static const int PLW = 128*33;   // one smem plane in words (stride 33: conflict-free)

// ---------------------------------------------------------------------------
// Phase A: approximate distance matrix, single tf32 MMA, D stored as bf16.
// D[m,n] = cn[n] - 2 * R[m,:].cb[n,:]; per-row min -> rowmin (atomicMin).
// ---------------------------------------------------------------------------
__global__ __launch_bounds__(256)
void vq_gemm_approx(const float* __restrict__ R, const float* __restrict__ cb,
                    const float* __restrict__ cn, __nv_bfloat16* __restrict__ D,
                    unsigned* __restrict__ rowmin)
{
    extern __shared__ uint32_t dyn[];
    uint32_t* sA = dyn;
    uint32_t* sB = dyn + PLW;
    unsigned* sMin = (unsigned*)(dyn + 2*PLW);

    const int tid  = threadIdx.x;
    const int lane = tid & 31;
    const int warp = tid >> 5;
    const int wm = warp & 1;
    const int wn = warp >> 1;
    const int m0 = blockIdx.x << 7;
    const int n0 = blockIdx.y << 7;

    float acc[4][4][4];
#pragma unroll
    for (int i = 0; i < 4; i++)
#pragma unroll
        for (int j = 0; j < 4; j++)
#pragma unroll
            for (int k = 0; k < 4; k++) acc[i][j][k] = 0.f;

    if (tid < 128) sMin[tid] = 0xFFFFFFFFu;

    for (int k0 = 0; k0 < 256; k0 += 32) {
#pragma unroll
        for (int i = 0; i < 4; i++) {
            int idx4 = tid + i*256;
            int m  = idx4 >> 3;
            int kq = idx4 & 7;
            int oa = m*33 + kq*4;
            float4 a = *(const float4*)(R  + (size_t)(m0 + m)*256 + k0 + kq*4);
            sA[oa+0] = f2tf(a.x); sA[oa+1] = f2tf(a.y);
            sA[oa+2] = f2tf(a.z); sA[oa+3] = f2tf(a.w);
            float4 b = *(const float4*)(cb + (size_t)(n0 + m)*256 + k0 + kq*4);
            sB[oa+0] = f2tf(b.x); sB[oa+1] = f2tf(b.y);
            sB[oa+2] = f2tf(b.z); sB[oa+3] = f2tf(b.w);
        }
        __syncthreads();

#pragma unroll
        for (int ks = 0; ks < 4; ks++) {
            const int kb = ks*8 + (lane & 3);
            uint32_t bf[4][2];
#pragma unroll
            for (int fn = 0; fn < 4; fn++) {
                int n = wn*32 + fn*8 + (lane >> 2);
                bf[fn][0] = sB[n*33 + kb];  bf[fn][1] = sB[n*33 + kb + 4];
            }
#pragma unroll
            for (int fm = 0; fm < 4; fm++) {
                int r = wm*64 + fm*16 + (lane >> 2);
                uint32_t af[4];
                af[0] = sA[r*33 + kb];     af[1] = sA[(r+8)*33 + kb];
                af[2] = sA[r*33 + kb+4];   af[3] = sA[(r+8)*33 + kb+4];
#pragma unroll
                for (int fn = 0; fn < 4; fn++)
                    mma_tf32(acc[fm][fn], af, bf[fn][0], bf[fn][1]);
            }
        }
        __syncthreads();
    }

    float cnv[4][2];
#pragma unroll
    for (int fn = 0; fn < 4; fn++) {
        int col = n0 + wn*32 + fn*8 + 2*(lane & 3);
        cnv[fn][0] = cn[col];
        cnv[fn][1] = cn[col + 1];
    }
#pragma unroll
    for (int fm = 0; fm < 4; fm++) {
#pragma unroll
        for (int h = 0; h < 2; h++) {
            int rl = wm*64 + fm*16 + (lane >> 2) + h*8;
            int rg = m0 + rl;
            float mn = 3.402823466e38f;
#pragma unroll
            for (int fn = 0; fn < 4; fn++) {
                int col = n0 + wn*32 + fn*8 + 2*(lane & 3);
                float vx = cnv[fn][0] - 2.f*acc[fm][fn][h*2 + 0];
                float vy = cnv[fn][1] - 2.f*acc[fm][fn][h*2 + 1];
                mn = fminf(mn, fminf(vx, vy));
                *(__nv_bfloat162*)(D + (size_t)rg*1024 + col) =
                    __floats2bfloat162_rn(vx, vy);
            }
            atomicMin(&sMin[rl], fenc(mn));
        }
    }
    __syncthreads();
    if (tid < 128) atomicMin(&rowmin[m0 + tid], sMin[tid]);
}

__global__ void init_rowmin_all(unsigned* rowmin) {
    rowmin[blockIdx.x*1024 + threadIdx.x] = 0xFFFFFFFFu;
}

// ---------------------------------------------------------------------------
// Phase B: one warp per token; batched bf16x2 scan (4 loads in flight),
// exact-FFMA rescore of candidates within EPS of the approx row-min,
// order-independent lowest-index tie-break, fused vq_update.
// ---------------------------------------------------------------------------
__global__ __launch_bounds__(256)
void vq_select_update(const __nv_bfloat16* __restrict__ D, const float* __restrict__ cb,
                      const float* __restrict__ cn,
                      const unsigned* __restrict__ rowmin,
                      float* __restrict__ resid, float* __restrict__ qsum,
                      float* __restrict__ idx_out, int stage,
                      double* __restrict__ lossAcc)
{
    __shared__ double sLoss[8];
    const int warp = threadIdx.x >> 5;
    const int lane = threadIdx.x & 31;
    const int t = blockIdx.x*8 + warp;

    const __nv_bfloat16* drow = D + (size_t)t*1024;
    const float thr = fdec(rowmin[t]) + 0.03f;

    float4 r0 = *(const float4*)(resid + (size_t)t*256 + lane*8);
    float4 r1 = *(const float4*)(resid + (size_t)t*256 + lane*8 + 4);

    float bestd = 3.402823466e38f;
    int   bestn = 0x7FFFFFFF;

    auto rescore = [&](int j) {
        const float* c = cb + (size_t)j*256;
        float4 c0 = *(const float4*)(c + lane*8);
        float4 c1 = *(const float4*)(c + lane*8 + 4);
        float dot = r0.x*c0.x + r0.y*c0.y + r0.z*c0.z + r0.w*c0.w
                  + r1.x*c1.x + r1.y*c1.y + r1.z*c1.z + r1.w*c1.w;
#pragma unroll
        for (int o = 16; o; o >>= 1)
            dot += __shfl_xor_sync(0xffffffffu, dot, o);
        float de = cn[j] - 2.f*dot;
        if (de < bestd || (de == bestd && j < bestn)) { bestd = de; bestn = j; }
    };

#pragma unroll
    for (int j0 = 0; j0 < 1024; j0 += 256) {
        float2 dd[4];
#pragma unroll
        for (int u = 0; u < 4; u++) {
            __nv_bfloat162 dv2 =
                *(const __nv_bfloat162*)(drow + j0 + u*64 + lane*2);
            dd[u] = __bfloat1622float2(dv2);
        }
#pragma unroll
        for (int u = 0; u < 4; u++) {
            unsigned me = __ballot_sync(0xffffffffu, dd[u].x <= thr);
            unsigned mo = __ballot_sync(0xffffffffu, dd[u].y <= thr);
            while (me) { int s = __ffs(me) - 1; me &= me - 1; rescore(j0 + u*64 + 2*s); }
            while (mo) { int s = __ffs(mo) - 1; mo &= mo - 1; rescore(j0 + u*64 + 2*s + 1); }
        }
    }

    const float* q = cb + (size_t)bestn*256;
    float4 q0 = *(const float4*)(q + lane*8);
    float4 q1 = *(const float4*)(q + lane*8 + 4);
    float4 s0 = *(float4*)(qsum + (size_t)t*256 + lane*8);
    float4 s1 = *(float4*)(qsum + (size_t)t*256 + lane*8 + 4);

    float ls = 0.f;
    {
        float d;
        d = q0.x-r0.x; ls += d*d;  d = q0.y-r0.y; ls += d*d;
        d = q0.z-r0.z; ls += d*d;  d = q0.w-r0.w; ls += d*d;
        d = q1.x-r1.x; ls += d*d;  d = q1.y-r1.y; ls += d*d;
        d = q1.z-r1.z; ls += d*d;  d = q1.w-r1.w; ls += d*d;
    }
    s0.x += q0.x; s0.y += q0.y; s0.z += q0.z; s0.w += q0.w;
    s1.x += q1.x; s1.y += q1.y; s1.z += q1.z; s1.w += q1.w;
    r0.x -= q0.x; r0.y -= q0.y; r0.z -= q0.z; r0.w -= q0.w;
    r1.x -= q1.x; r1.y -= q1.y; r1.z -= q1.z; r1.w -= q1.w;
    *(float4*)(qsum  + (size_t)t*256 + lane*8)     = s0;
    *(float4*)(qsum  + (size_t)t*256 + lane*8 + 4) = s1;
    *(float4*)(resid + (size_t)t*256 + lane*8)     = r0;
    *(float4*)(resid + (size_t)t*256 + lane*8 + 4) = r1;

#pragma unroll
    for (int o = 16; o; o >>= 1) ls += __shfl_down_sync(0xffffffffu, ls, o);
    if (lane == 0) {
        sLoss[warp] = (double)ls;
        idx_out[(t >> 12)*16384 + stage*4096 + (t & 4095)] = (float)bestn;
    }
    __syncthreads();
    if (threadIdx.x == 0) {
        double tot = 0.0;
#pragma unroll
        for (int w = 0; w < 8; w++) tot += sLoss[w];
        atomicAdd(lossAcc + stage, tot);
    }
}

// ---------------------------------------------------------------------------
// enc1 (4x4 s2 p1, Cin=3 -> Cout=64) as implicit GEMM. M=128 px (one output
// row), N=64, K=48 (16 taps x 3 ci), single smem stage. Coalesced stores.
// ---------------------------------------------------------------------------
__global__ __launch_bounds__(256)
void conv1_ffma(const float* __restrict__ in, const float* __restrict__ wt,
                const float* __restrict__ bias, float* __restrict__ out)
{
    __shared__ float sA[48*128];
    __shared__ float sB[48*64];
    const int tid = threadIdx.x;
    const int tx = tid & 31;          // px group (x4, strided 32)
    const int ty = tid >> 5;          // co group (x8)
    const int b  = blockIdx.x >> 7;
    const int yr = blockIdx.x & 127;  // output row

    // load A: 48 x 128 (k = tap*3 + ci)
    for (int idx = tid; idx < 48*128; idx += 256) {
        int k  = idx >> 7, px = idx & 127;
        int tap = k/3, ci = k - tap*3;
        int kh = tap >> 2, kw = tap & 3;
        int iy = yr*2 + kh - 1;
        int ix = px*2 + kw - 1;
        float v = 0.f;
        if ((unsigned)iy < 256u && (unsigned)ix < 256u)
            v = in[((size_t)(b*3 + ci)*256 + iy)*256 + ix];
        sA[idx] = v;
    }
    for (int idx = tid; idx < 48*64; idx += 256)
        sB[idx] = wt[idx];
    __syncthreads();

    float acc[4][8];
#pragma unroll
    for (int i = 0; i < 4; i++)
#pragma unroll
        for (int j = 0; j < 8; j++) acc[i][j] = 0.f;

#pragma unroll
    for (int kk = 0; kk < 48; kk++) {
        float av[4];
#pragma unroll
        for (int i = 0; i < 4; i++) av[i] = sA[kk*128 + tx + 32*i];
        float4 b0 = *(const float4*)&sB[kk*64 + ty*8];
        float4 b1 = *(const float4*)&sB[kk*64 + ty*8 + 4];
        float bv[8] = {b0.x,b0.y,b0.z,b0.w,b1.x,b1.y,b1.z,b1.w};
#pragma unroll
        for (int i = 0; i < 4; i++)
#pragma unroll
            for (int j = 0; j < 8; j++) acc[i][j] += av[i]*bv[j];
    }

#pragma unroll
    for (int j = 0; j < 8; j++) {
        int co = ty*8 + j;
        float bv = bias[co];
        float* p = out + ((size_t)(b*64 + co)*128 + yr)*128;
#pragma unroll
        for (int i = 0; i < 4; i++)
            p[tx + 32*i] = fmaxf(acc[i][j] + bv, 0.f);
    }
}

// ---------------------------------------------------------------------------
// Implicit-GEMM FFMA conv (3x3 s1 or 4x4 s2, pad 1). Output 64x64 per image.
// Double-buffered smem, register-staged prefetch, single sync per chunk.
// ---------------------------------------------------------------------------
template<int KSZ, int S>
__global__ __launch_bounds__(256, 2)
void conv_ffma(const float* __restrict__ in, const float* __restrict__ wt,
               const float* __restrict__ bias, float* __restrict__ out,
               int Cin, int Hin, int Win, int Cout, int relu)
{
    __shared__ float sA[2][16*128];
    __shared__ float sB[2][16*128];
    const int tid = threadIdx.x;
    const int tx = tid & 15;
    const int ty = tid >> 4;
    const int m0  = blockIdx.x << 7;
    const int co0 = blockIdx.y << 7;
    const int b   = m0 >> 12;
    const int y0  = (m0 & 4095) >> 6;
    const int cpt = Cin >> 4;
    const int NCH = KSZ*KSZ*cpt;

    float acc[8][8];
#pragma unroll
    for (int i = 0; i < 8; i++)
#pragma unroll
        for (int j = 0; j < 8; j++) acc[i][j] = 0.f;

    float ra[8], rb[8];

    auto loadc = [&](int q) {
        int tap = q / cpt;
        int ci0 = (q - tap*cpt) << 4;
        int dy = tap/KSZ - 1, dx = tap%KSZ - 1;
#pragma unroll
        for (int v = 0; v < 8; v++) {
            int idx = tid + v*256;
            int ci = idx >> 7, pix = idx & 127;
            int iy = (y0 + (pix >> 6))*S + dy;
            int ix = (pix & 63)*S + dx;
            float val = 0.f;
            if ((unsigned)iy < (unsigned)Hin && (unsigned)ix < (unsigned)Win)
                val = in[((size_t)(b*Cin + ci0 + ci)*Hin + iy)*Win + ix];
            ra[v] = val;
            rb[v] = wt[((size_t)tap*Cin + ci0 + ci)*Cout + co0 + pix];
        }
    };
    auto storec = [&](int buf) {
#pragma unroll
        for (int v = 0; v < 8; v++) {
            int idx = tid + v*256;
            int ci = idx >> 7, pix = idx & 127;
            sA[buf][ci*128 + pix] = ra[v];
            sB[buf][ci*128 + pix] = rb[v];
        }
    };

    loadc(0); storec(0); __syncthreads();
    for (int q = 0; q < NCH; q++) {
        if (q + 1 < NCH) loadc(q + 1);
        const float* pA = sA[q & 1];
        const float* pB = sB[q & 1];
#pragma unroll
        for (int kk = 0; kk < 16; kk++) {
            float4 a0 = *(const float4*)&pA[kk*128 + tx*8];
            float4 a1 = *(const float4*)&pA[kk*128 + tx*8 + 4];
            float4 b0 = *(const float4*)&pB[kk*128 + ty*8];
            float4 b1 = *(const float4*)&pB[kk*128 + ty*8 + 4];
            float av[8] = {a0.x,a0.y,a0.z,a0.w,a1.x,a1.y,a1.z,a1.w};
            float bv[8] = {b0.x,b0.y,b0.z,b0.w,b1.x,b1.y,b1.z,b1.w};
#pragma unroll
            for (int i = 0; i < 8; i++)
#pragma unroll
                for (int j = 0; j < 8; j++) acc[i][j] += av[i]*bv[j];
        }
        if (q + 1 < NCH) storec((q + 1) & 1);
        __syncthreads();
    }

    const int yr = y0 + (tx >> 3);
    const int xc = (tx*8) & 63;
#pragma unroll
    for (int j = 0; j < 8; j++) {
        int co = co0 + ty*8 + j;
        float bv = bias[co];
        float4 v0, v1;
        v0.x = acc[0][j]+bv; v0.y = acc[1][j]+bv; v0.z = acc[2][j]+bv; v0.w = acc[3][j]+bv;
        v1.x = acc[4][j]+bv; v1.y = acc[5][j]+bv; v1.z = acc[6][j]+bv; v1.w = acc[7][j]+bv;
        if (relu) {
            v0.x = fmaxf(v0.x,0.f); v0.y = fmaxf(v0.y,0.f); v0.z = fmaxf(v0.z,0.f); v0.w = fmaxf(v0.w,0.f);
            v1.x = fmaxf(v1.x,0.f); v1.y = fmaxf(v1.y,0.f); v1.z = fmaxf(v1.z,0.f); v1.w = fmaxf(v1.w,0.f);
        }
        float* p = out + ((size_t)(b*Cout + co)*4096 + yr*64 + xc);
        *(float4*)p = v0;
        *(float4*)(p + 4) = v1;
    }
}

// ---------------------------------------------------------------------------
// Implicit-GEMM FFMA convT (k4 s2 p1), parity-decomposed, Cout=64, relu.
// Coalesced parity stores (mx = tx + 32*i).
// ---------------------------------------------------------------------------
__global__ __launch_bounds__(256, 2)
void convT_ffma(const float* __restrict__ in, const float* __restrict__ wtT,
                const float* __restrict__ bias, float* __restrict__ out,
                int Cin, int Hin, int Win, int wsh, int hwsh)
{
    __shared__ float sA[2][16*256];
    __shared__ float sB[2][16*64];
    const int tid = threadIdx.x;
    const int tx = tid & 31;
    const int ty = tid >> 5;
    const int P0 = blockIdx.x << 8;
    const int b   = P0 >> hwsh;
    const int lp  = P0 & ((1 << hwsh) - 1);
    const int my0 = lp >> wsh;
    const int p  = blockIdx.z;
    const int ey = p >> 1, ex = p & 1;
    const float* wtp = wtT + (size_t)p*4*Cin*64;
    const int Wo  = Win*2;
    const int HWo = (Hin*Win)*4;
    const int cpt = Cin >> 4;
    const int NCH = 4*cpt;

    float acc[8][8];
#pragma unroll
    for (int i = 0; i < 8; i++)
#pragma unroll
        for (int j = 0; j < 8; j++) acc[i][j] = 0.f;

    float ra[16], rb[4];

    auto loadc = [&](int q) {
        int t = q / cpt;
        int ci0 = (q - t*cpt) << 4;
        int jy = t >> 1, jx = t & 1;
        int ry = (ey == 0) ? (jy == 0 ? 0 : -1) : (jy == 0 ? 1 : 0);
        int rx = (ex == 0) ? (jx == 0 ? 0 : -1) : (jx == 0 ? 1 : 0);
#pragma unroll
        for (int v = 0; v < 16; v++) {
            int idx = tid + v*256;
            int ci = idx >> 8, pix = idx & 255;
            int iy = my0 + (pix >> wsh) + ry;
            int ix = (pix & (Win-1)) + rx;
            float val = 0.f;
            if ((unsigned)iy < (unsigned)Hin && (unsigned)ix < (unsigned)Win)
                val = in[((size_t)(b*Cin + ci0 + ci)*Hin + iy)*Win + ix];
            ra[v] = val;
        }
#pragma unroll
        for (int v = 0; v < 4; v++) {
            int idx = tid + v*256;
            int ci = idx >> 6, n = idx & 63;
            rb[v] = wtp[((size_t)t*Cin + ci0 + ci)*64 + n];
        }
    };
    auto storec = [&](int buf) {
#pragma unroll
        for (int v = 0; v < 16; v++) {
            int idx = tid + v*256;
            int ci = idx >> 8, pix = idx & 255;
            sA[buf][ci*256 + pix] = ra[v];
        }
#pragma unroll
        for (int v = 0; v < 4; v++) {
            int idx = tid + v*256;
            int ci = idx >> 6, n = idx & 63;
            sB[buf][ci*64 + n] = rb[v];
        }
    };

    loadc(0); storec(0); __syncthreads();
    for (int q = 0; q < NCH; q++) {
        if (q + 1 < NCH) loadc(q + 1);
        const float* pA = sA[q & 1];
        const float* pB = sB[q & 1];
#pragma unroll
        for (int kk = 0; kk < 16; kk++) {
            float av[8];
#pragma unroll
            for (int i = 0; i < 8; i++)
                av[i] = pA[kk*256 + tx + 32*i];
            float4 b0 = *(const float4*)&pB[kk*64 + ty*8];
            float4 b1 = *(const float4*)&pB[kk*64 + ty*8 + 4];
            float bv[8] = {b0.x,b0.y,b0.z,b0.w,b1.x,b1.y,b1.z,b1.w};
#pragma unroll
            for (int i = 0; i < 8; i++)
#pragma unroll
                for (int j = 0; j < 8; j++) acc[i][j] += av[i]*bv[j];
        }
        if (q + 1 < NCH) storec((q + 1) & 1);
        __syncthreads();
    }

#pragma unroll
    for (int j = 0; j < 8; j++) {
        int co = ty*8 + j;
        float bv = bias[co];
        float* pb = out + (size_t)(b*64 + co)*HWo + ex;
#pragma unroll
        for (int i = 0; i < 8; i++) {
            int gp = lp + tx + 32*i;
            int my = gp >> wsh;
            int mx = gp & (Win-1);
            int oy = 2*my + ey;
            pb[oy*Wo + 2*mx] = fmaxf(acc[i][j] + bv, 0.f);
        }
    }
}

// ---------------------------------------------------------------------------
// convT4 (k4 s2 p1, Cin=64 -> Cout=3, tanh): per-parity 4-tap form.
// Weights wp[ci][pt(16)][co pad 4]. Dynamic smem 54784 B.
// ---------------------------------------------------------------------------
__global__ __launch_bounds__(256)
void convT4_ffma(const float* __restrict__ in, const float* __restrict__ wp,
                 const float* __restrict__ bias, float* __restrict__ out)
{
    extern __shared__ float dynf[];
    float* sA = dynf;              // [16 ci][3 rows][264]
    float* sB = dynf + 16*792;     // [16 ci][16 pt][4]

    const int tid = threadIdx.x;
    const int b  = blockIdx.x >> 8;
    const int my = blockIdx.x & 255;
    const float* inb = in + (size_t)b*64*65536;

    float acc[12];
#pragma unroll
    for (int i = 0; i < 12; i++) acc[i] = 0.f;

    for (int ci0 = 0; ci0 < 64; ci0 += 16) {
        for (int idx = tid; idx < 16*3*258; idx += 256) {
            int ci = idx / 774;
            int rem = idx - ci*774;
            int r = rem / 258, c = rem - r*258;
            int iy = my - 1 + r, ix = c - 1;
            float v = 0.f;
            if ((unsigned)iy < 256u && (unsigned)ix < 256u)
                v = inb[((size_t)(ci0 + ci)*256 + iy)*256 + ix];
            sA[ci*792 + r*264 + c] = v;
        }
        for (int idx = tid; idx < 1024; idx += 256)
            sB[idx] = wp[ci0*64 + idx];
        __syncthreads();

        for (int ci = 0; ci < 16; ci++) {
            float n[9];
#pragma unroll
            for (int r = 0; r < 3; r++)
#pragma unroll
                for (int c = 0; c < 3; c++)
                    n[r*3 + c] = sA[ci*792 + r*264 + c + tid];
#pragma unroll
            for (int pt = 0; pt < 16; pt++) {
                const int p = pt >> 2, t = pt & 3;
                const int ey = p >> 1, ex = p & 1;
                const int jy = t >> 1, jx = t & 1;
                const int ry = (ey == 0) ? (jy == 0 ? 0 : -1) : (jy == 0 ? 1 : 0);
                const int rx = (ex == 0) ? (jx == 0 ? 0 : -1) : (jx == 0 ? 1 : 0);
                const int ni = (1 + ry)*3 + (1 + rx);
                float a = n[ni];
                const float4 w = *(const float4*)&sB[ci*64 + pt*4];
                acc[p*3 + 0] += a*w.x;
                acc[p*3 + 1] += a*w.y;
                acc[p*3 + 2] += a*w.z;
            }
        }
        __syncthreads();
    }

    const int mx = tid;
#pragma unroll
    for (int p = 0; p < 4; p++) {
        int ey = p >> 1, ex = p & 1;
        int oy = 2*my + ey;
#pragma unroll
        for (int co = 0; co < 3; co++) {
            float v = tanhf(acc[p*3 + co] + bias[co]);
            out[(((size_t)b*3 + co)*512 + oy)*512 + 2*mx + ex] = v;
        }
    }
}

// ---------------------------------------------------------------------------
// Fused weight repack (single launch)
// ---------------------------------------------------------------------------
__device__ __forceinline__ void rp_conv(const float* w, float* wt,
                                        int Cin, int Cout, int KK, int idx)
{
    int co = idx % Cout; int r = idx / Cout;
    int ci = r % Cin;    int tap = r / Cin;
    wt[idx] = w[(co*Cin + ci)*KK + tap];
}

__device__ __forceinline__ void rp_convT(const float* w, float* wtT,
                                         int Cin, int Cout, int idx)
{
    int co = idx % Cout; int r = idx / Cout;
    int ci = r % Cin;    int pt = r / Cin;
    int p = pt >> 2, t = pt & 3;
    int ey = p >> 1, ex = p & 1;
    int jy = t >> 1, jx = t & 1;
    int ky = (ey == 0) ? (jy == 0 ? 1 : 3) : (jy == 0 ? 0 : 2);
    int kx = (ex == 0) ? (jx == 0 ? 1 : 3) : (jx == 0 ? 0 : 2);
    wtT[idx] = w[((ci*Cout + co)*4 + ky)*4 + kx];
}

// dec_w4 (ci=64, co=3, 4, 4) -> wp[ci][pt(16)][co pad 4]
__device__ __forceinline__ void rp_w4(const float* w, float* wp, int idx)
{
    int ci = idx >> 6;
    int rem = idx & 63;
    int pt = rem >> 2, c = rem & 3;
    float v = 0.f;
    if (c < 3) {
        int p = pt >> 2, t = pt & 3;
        int ey = p >> 1, ex = p & 1;
        int jy = t >> 1, jx = t & 1;
        int ky = (ey == 0) ? (jy == 0 ? 1 : 3) : (jy == 0 ? 0 : 2);
        int kx = (ex == 0) ? (jx == 0 ? 1 : 3) : (jx == 0 ? 0 : 2);
        v = w[((ci*3 + c)*4 + ky)*4 + kx];
    }
    wp[idx] = v;
}

__global__ void repack_all(const float* ew1, const float* ew2, const float* ew3,
                           const float* ew4, const float* dw1, const float* dw2,
                           const float* dw3, const float* dw4,
                           float* wt_e1, float* wt_e2, float* wt_e3, float* wt_e4,
                           float* wt_d1, float* wtT_d2, float* wtT_d3, float* w4p)
{
    int idx = blockIdx.x*256 + threadIdx.x;
    if (idx < 3072)   { rp_conv(ew1, wt_e1, 3, 64, 16, idx); return; }
    idx -= 3072;
    if (idx < 131072) { rp_conv(ew2, wt_e2, 64, 128, 16, idx); return; }
    idx -= 131072;
    if (idx < 294912) { rp_conv(ew3, wt_e3, 128, 256, 9, idx); return; }
    idx -= 294912;
    if (idx < 589824) { rp_conv(ew4, wt_e4, 256, 256, 9, idx); return; }
    idx -= 589824;
    if (idx < 294912) { rp_conv(dw1, wt_d1, 256, 128, 9, idx); return; }
    idx -= 294912;
    if (idx < 131072) { rp_convT(dw2, wtT_d2, 128, 64, idx); return; }
    idx -= 131072;
    if (idx < 65536)  { rp_convT(dw3, wtT_d3, 64, 64, idx); return; }
    idx -= 65536;
    if (idx < 4096)   { rp_w4(dw4, w4p, idx); }
}

// ---------------------------------------------------------------------------
// Helpers
// ---------------------------------------------------------------------------
__global__ void cnorm_kernel(const float* __restrict__ cb, float* __restrict__ cn) {
    int row  = (blockIdx.x*blockDim.x + threadIdx.x) >> 5;
    int lane = threadIdx.x & 31;
    if (row >= 4096) return;
    const float* p = cb + (size_t)row*256;
    float s = 0.f;
    for (int c = lane; c < 256; c += 32) { float v = p[c]; s += v*v; }
#pragma unroll
    for (int o = 16; o; o >>= 1) s += __shfl_down_sync(0xffffffffu, s, o);
    if (!lane) cn[row] = s;
}

__global__ void zero_loss(double* l) { if (threadIdx.x < 4) l[threadIdx.x] = 0.0; }

__global__ void write_loss(const double* __restrict__ l, float* __restrict__ o) {
    if (threadIdx.x < 4)
        o[threadIdx.x] = (float)(l[threadIdx.x] * (1.0/(65536.0*256.0)));
}

__global__ void z_to_tokens(const float* __restrict__ z,
                            float* __restrict__ resid, float* __restrict__ qsum)
{
    __shared__ float t[32][33];
    int b  = blockIdx.z;
    int s0 = blockIdx.x*32;
    int c0 = blockIdx.y*32;
    int x  = threadIdx.x;
    for (int y = threadIdx.y; y < 32; y += 8)
        t[y][x] = z[((size_t)b*256 + c0 + y)*4096 + s0 + x];
    __syncthreads();
    for (int y = threadIdx.y; y < 32; y += 8) {
        size_t o = ((size_t)b*4096 + s0 + y)*256 + c0 + x;
        resid[o] = t[x][y];
        qsum[o]  = 0.f;
    }
}

__global__ void tokens_to_z(const float* __restrict__ qsum,
                            float* __restrict__ z1, float* __restrict__ z2)
{
    __shared__ float t[32][33];
    int b  = blockIdx.z;
    int c0 = blockIdx.x*32;
    int s0 = blockIdx.y*32;
    int x  = threadIdx.x;
    for (int y = threadIdx.y; y < 32; y += 8)
        t[y][x] = qsum[((size_t)b*4096 + s0 + y)*256 + c0 + x];
    __syncthreads();
    for (int y = threadIdx.y; y < 32; y += 8) {
        float v = t[x][y];
        size_t o = ((size_t)b*256 + c0 + y)*4096 + s0 + x;
        z1[o] = v; z2[o] = v;
    }
}

// ---------------------------------------------------------------------------
// Launch
// ---------------------------------------------------------------------------
extern "C" void kernel_launch(void* const* d_in, const int* in_sizes, int n_in,
                              void* d_out, int out_size)
{
    const float* x   = (const float*)d_in[0];
    const float* ew1 = (const float*)d_in[1];  const float* eb1 = (const float*)d_in[2];
    const float* ew2 = (const float*)d_in[3];  const float* eb2 = (const float*)d_in[4];
    const float* ew3 = (const float*)d_in[5];  const float* eb3 = (const float*)d_in[6];
    const float* ew4 = (const float*)d_in[7];  const float* eb4 = (const float*)d_in[8];
    const float* cbs = (const float*)d_in[9];
    const float* dw1 = (const float*)d_in[10]; const float* db1 = (const float*)d_in[11];
    const float* dw2 = (const float*)d_in[12]; const float* db2 = (const float*)d_in[13];
    const float* dw3 = (const float*)d_in[14]; const float* db3 = (const float*)d_in[15];
    const float* dw4 = (const float*)d_in[16]; const float* db4 = (const float*)d_in[17];
    float* out = (float*)d_out;

    float *h1, *h2, *h3, *z, *resid, *qsum, *cnorm, *w4p, *wt, *wtT, *d3;
    double* loss; unsigned* rowmin;
    cudaGetSymbolAddress((void**)&h1,    g_h1);
    cudaGetSymbolAddress((void**)&h2,    g_h2);
    cudaGetSymbolAddress((void**)&h3,    g_h3);
    cudaGetSymbolAddress((void**)&z,     g_z);
    cudaGetSymbolAddress((void**)&resid, g_resid);
    cudaGetSymbolAddress((void**)&qsum,  g_qsum);
    cudaGetSymbolAddress((void**)&loss,  g_loss);
    cudaGetSymbolAddress((void**)&cnorm, g_cnorm);
    cudaGetSymbolAddress((void**)&rowmin,g_rowmin);
    cudaGetSymbolAddress((void**)&w4p,   g_w4p);
    cudaGetSymbolAddress((void**)&wt,    g_wt);
    cudaGetSymbolAddress((void**)&wtT,   g_wtT);
    cudaGetSymbolAddress((void**)&d3,    g_d3);

    float* wt_e1  = wt;                               // 16*3*64    = 3072
    float* wt_e2  = wt + 3072;                        // 16*64*128  = 131072
    float* wt_e3  = wt_e2 + 131072;                   // 9*128*256  = 294912
    float* wt_e4  = wt_e3 + 294912;                   // 9*256*256  = 589824
    float* wt_d1  = wt_e4 + 589824;                   // 9*256*128  = 294912
    float* wtT_d2 = wtT;                              // 16*128*64  = 131072
    float* wtT_d3 = wtT + 131072;                     // 16*64*64   = 65536

    // output layout: recon | indices | commit_loss | quantized
    float* recO   = out;
    float* idxO   = out + 12582912;
    float* lossO  = idxO + 262144;
    float* quantO = lossO + 4;

    const int PA_SMEM  = 2*PLW*4 + 512;               // 34304
    const int CT4_SMEM = (16*792 + 1024)*4;           // 54784
    cudaFuncSetAttribute(vq_gemm_approx, cudaFuncAttributeMaxDynamicSharedMemorySize, PA_SMEM);
    cudaFuncSetAttribute(convT4_ffma,    cudaFuncAttributeMaxDynamicSharedMemorySize, CT4_SMEM);

    // prep (regions total 1514496 -> 5916 blocks)
    repack_all     <<<5916, 256>>>(ew1, ew2, ew3, ew4, dw1, dw2, dw3, dw4,
                                   wt_e1, wt_e2, wt_e3, wt_e4, wt_d1,
                                   wtT_d2, wtT_d3, w4p);
    cnorm_kernel   <<<512, 256>>>(cbs, cnorm);
    zero_loss      <<<1, 32>>>(loss);
    init_rowmin_all<<<256, 1024>>>(rowmin);

    // ---- encoder (exact fp32) ----
    conv1_ffma<<<2048, 256>>>(x, wt_e1, eb1, h1);
    conv_ffma<4,2><<<dim3(512, 1), 256>>>(h1, wt_e2, eb2, h2,  64, 128, 128, 128, 1);
    conv_ffma<3,1><<<dim3(512, 2), 256>>>(h2, wt_e3, eb3, h3, 128,  64,  64, 256, 1);
    conv_ffma<3,1><<<dim3(512, 2), 256>>>(h3, wt_e4, eb4, z,  256,  64,  64, 256, 0);

    // ---- residual VQ: single-MMA tf32 approx distances (bf16 D) + exact rescore ----
    z_to_tokens<<<dim3(128, 8, 16), dim3(32, 8)>>>(z, resid, qsum);
    __nv_bfloat16* Dh = (__nv_bfloat16*)d3;
    for (int s = 0; s < 4; s++) {
        vq_gemm_approx  <<<dim3(512, 8), 256, PA_SMEM>>>(resid, cbs + (size_t)s*1024*256,
                                                         cnorm + s*1024, Dh, rowmin + s*65536);
        vq_select_update<<<8192, 256>>>(Dh, cbs + (size_t)s*1024*256, cnorm + s*1024,
                                        rowmin + s*65536, resid, qsum, idxO, s, loss);
    }
    write_loss <<<1, 32>>>(loss, lossO);
    tokens_to_z<<<dim3(8, 128, 16), dim3(32, 8)>>>(qsum, z, quantO);

    // ---- decoder (FFMA, exact) ----
    conv_ffma<3,1><<<dim3(512, 1), 256>>>(z, wt_d1, db1, h2, 256, 64, 64, 128, 1);
    convT_ffma<<<dim3( 256, 1, 4), 256>>>(h2, wtT_d2, db2, h1, 128,  64,  64, 6, 12);
    convT_ffma<<<dim3(1024, 1, 4), 256>>>(h1, wtT_d3, db3, d3,  64, 128, 128, 7, 14);
    convT4_ffma<<<4096, 256, CT4_SMEM>>>(d3, w4p, db4, recO);
}